// round 1
// baseline (speedup 1.0000x reference)
#include <cuda_runtime.h>

#define BB 4
#define NN 2048
#define EE 768
#define HH 12
#define DD 64
#define RD 32

// Scratch (allocation-free contract: __device__ globals)
__device__ float g_qh[(size_t)BB * HH * NN * DD];
__device__ float g_kh[(size_t)BB * HH * NN * DD];
__device__ float g_vh[(size_t)BB * HH * NN * DD];
__device__ float g_y [(size_t)BB * NN * EE];

// ---------------------------------------------------------------------------
// Kernel 1: per-(b,n) row: split heads, RMSNorm(q,k), xPos RoPE, transpose to
// (B,H,N,D); also materialize V in (B,H,N,D). 12 warps/block, 1 warp = 1 head,
// lane l owns the interleaved rope pair (2l, 2l+1).
// ---------------------------------------------------------------------------
__global__ __launch_bounds__(384) void prep_kernel(
    const float* __restrict__ q, const float* __restrict__ k,
    const float* __restrict__ v,
    const float* __restrict__ qs, const float* __restrict__ ks)
{
    const int row = blockIdx.x;          // b*NN + n
    const int b = row / NN;
    const int n = row - b * NN;
    const int w = threadIdx.x >> 5;      // head 0..11
    const int l = threadIdx.x & 31;      // lane

    const size_t ibase = (size_t)row * EE + w * DD + 2 * l;
    float x0 = q[ibase], x1 = q[ibase + 1];
    float y0 = k[ibase], y1 = k[ibase + 1];
    float v0 = v[ibase], v1 = v[ibase + 1];

    // RMS over the 64-dim head (pairwise partial + warp reduce)
    float sq = x0 * x0 + x1 * x1;
    float sk = y0 * y0 + y1 * y1;
    #pragma unroll
    for (int off = 16; off; off >>= 1) {
        sq += __shfl_xor_sync(0xffffffffu, sq, off);
        sk += __shfl_xor_sync(0xffffffffu, sk, off);
    }
    const float rq = rsqrtf(sq * (1.0f / DD) + 1e-6f);
    const float rk = rsqrtf(sk * (1.0f / DD) + 1e-6f);
    x0 *= rq * qs[2 * l]; x1 *= rq * qs[2 * l + 1];
    y0 *= rk * ks[2 * l]; y1 *= rk * ks[2 * l + 1];

    // xPos RoPE on the first RD=32 dims (pairs 0..15)
    if (l < 16) {
        const float freq = powf(10000.0f, -(float)l / 16.0f);
        float s, c;
        sincosf((float)n * freq, &s, &c);
        const float base  = (2.0f * l + 0.4f * RD) / (1.4f * RD);
        const float power = ((float)n - (float)(NN / 2)) * (1.0f / 512.0f);
        const float sc  = powf(base,  power);
        const float isc = powf(base, -power);
        const float nx0 = (x0 * c - x1 * s) * sc;
        const float nx1 = (x1 * c + x0 * s) * sc;
        const float ny0 = (y0 * c - y1 * s) * isc;
        const float ny1 = (y1 * c + y0 * s) * isc;
        x0 = nx0; x1 = nx1; y0 = ny0; y1 = ny1;
    }

    const size_t obase = (((size_t)b * HH + w) * NN + n) * DD + 2 * l;
    *(float2*)(g_qh + obase) = make_float2(x0, x1);
    *(float2*)(g_kh + obase) = make_float2(y0, y1);
    *(float2*)(g_vh + obase) = make_float2(v0, v1);
}

// ---------------------------------------------------------------------------
// Kernel 2: causal flash attention. 1 thread = 1 query row (q, o in regs),
// K/V streamed through smem in BC=32 key tiles, online softmax with per-tile
// rescale. Grid y = b*H head, grid x reversed so heavy diagonal blocks launch
// first (wave balance).
// ---------------------------------------------------------------------------
#define BR 128
#define BC 32

__global__ __launch_bounds__(BR, 2) void attn_kernel()
{
    const int qb = (gridDim.x - 1) - blockIdx.x;   // heavy-first
    const int bh = blockIdx.y;
    const int t  = threadIdx.x;
    const int qg = qb * BR + t;

    const float* __restrict__ Q = g_qh + (size_t)bh * NN * DD;
    const float* __restrict__ K = g_kh + (size_t)bh * NN * DD;
    const float* __restrict__ V = g_vh + (size_t)bh * NN * DD;

    __shared__ float k_sm[BC * DD];
    __shared__ float v_sm[BC * DD];

    float qreg[DD], o[DD];
    #pragma unroll
    for (int d = 0; d < DD; d += 4) {
        float4 t4 = *(const float4*)(Q + (size_t)qg * DD + d);
        qreg[d] = t4.x; qreg[d + 1] = t4.y; qreg[d + 2] = t4.z; qreg[d + 3] = t4.w;
        o[d] = 0.f; o[d + 1] = 0.f; o[d + 2] = 0.f; o[d + 3] = 0.f;
    }
    float m = -1e30f, lsum = 0.f;

    const int ntiles = ((qb + 1) * BR) / BC;
    for (int j = 0; j < ntiles; j++) {
        const int kb = j * BC;
        __syncthreads();
        {   // BC*DD = 2048 floats = 512 float4 per array; 128 threads x 4
            const float4* kg4 = (const float4*)(K + (size_t)kb * DD);
            const float4* vg4 = (const float4*)(V + (size_t)kb * DD);
            #pragma unroll
            for (int i = 0; i < 4; i++) {
                ((float4*)k_sm)[t + i * BR] = kg4[t + i * BR];
                ((float4*)v_sm)[t + i * BR] = vg4[t + i * BR];
            }
        }
        __syncthreads();

        float sreg[BC];
        float mt = -1e30f;
        #pragma unroll
        for (int c = 0; c < BC; c++) {
            const float4* kr = (const float4*)(k_sm + c * DD);
            float s0 = 0.f, s1 = 0.f, s2 = 0.f, s3 = 0.f;
            #pragma unroll
            for (int d4 = 0; d4 < 16; d4++) {
                float4 kk = kr[d4];
                s0 += qreg[4 * d4 + 0] * kk.x;
                s1 += qreg[4 * d4 + 1] * kk.y;
                s2 += qreg[4 * d4 + 2] * kk.z;
                s3 += qreg[4 * d4 + 3] * kk.w;
            }
            float s = ((s0 + s1) + (s2 + s3)) * 0.125f;   // 1/sqrt(64)
            if (kb + c > qg) s = -1e30f;                  // causal mask
            sreg[c] = s;
            mt = fmaxf(mt, s);
        }

        const float mnew  = fmaxf(m, mt);
        const float alpha = __expf(m - mnew);
        lsum *= alpha;
        #pragma unroll
        for (int d = 0; d < DD; d++) o[d] *= alpha;

        #pragma unroll
        for (int c = 0; c < BC; c++) {
            const float p = __expf(sreg[c] - mnew);
            lsum += p;
            const float4* vr = (const float4*)(v_sm + c * DD);
            #pragma unroll
            for (int d4 = 0; d4 < 16; d4++) {
                float4 vv = vr[d4];
                o[4 * d4 + 0] += p * vv.x;
                o[4 * d4 + 1] += p * vv.y;
                o[4 * d4 + 2] += p * vv.z;
                o[4 * d4 + 3] += p * vv.w;
            }
        }
        m = mnew;
    }

    const float inv = __fdividef(1.0f, lsum);
    const int b = bh / HH, h = bh - b * HH;
    float* yo = g_y + ((size_t)b * NN + qg) * EE + h * DD;
    #pragma unroll
    for (int d = 0; d < DD; d += 4) {
        *(float4*)(yo + d) = make_float4(o[d] * inv, o[d + 1] * inv,
                                         o[d + 2] * inv, o[d + 3] * inv);
    }
}

// ---------------------------------------------------------------------------
// Kernel 3: out = Y @ W^T + b.  Y:(8192x768) row-major, W:(768x768) row-major
// (both K-contiguous). Classic 128x128x8 SGEMM, 8x8 micro-tiles, 256 threads.
// All dims divide tiles exactly (8192/128, 768/128, 768/8) -> no guards.
// ---------------------------------------------------------------------------
__global__ __launch_bounds__(256) void proj_kernel(
    const float* __restrict__ W, const float* __restrict__ bias,
    float* __restrict__ out)
{
    __shared__ float As[8][128];
    __shared__ float Bs[8][128];
    const int t  = threadIdx.x;
    const int bm = blockIdx.y * 128;
    const int bn = blockIdx.x * 128;
    const int arow = t >> 1;
    const int acol = (t & 1) * 4;
    const int tx = t & 15;   // column group
    const int ty = t >> 4;   // row group

    float acc[8][8];
    #pragma unroll
    for (int i = 0; i < 8; i++)
        #pragma unroll
        for (int j = 0; j < 8; j++) acc[i][j] = 0.f;

    const float* Ag = g_y + (size_t)(bm + arow) * EE + acol;
    const float* Bg = W   + (size_t)(bn + arow) * EE + acol;

    for (int k0 = 0; k0 < EE; k0 += 8) {
        const float4 av = *(const float4*)(Ag + k0);
        const float4 bv = *(const float4*)(Bg + k0);
        __syncthreads();
        As[acol + 0][arow] = av.x; As[acol + 1][arow] = av.y;
        As[acol + 2][arow] = av.z; As[acol + 3][arow] = av.w;
        Bs[acol + 0][arow] = bv.x; Bs[acol + 1][arow] = bv.y;
        Bs[acol + 2][arow] = bv.z; Bs[acol + 3][arow] = bv.w;
        __syncthreads();

        #pragma unroll
        for (int kk = 0; kk < 8; kk++) {
            float a[8], bwv[8];
            *(float4*)&a[0]   = *(const float4*)&As[kk][ty * 4];
            *(float4*)&a[4]   = *(const float4*)&As[kk][64 + ty * 4];
            *(float4*)&bwv[0] = *(const float4*)&Bs[kk][tx * 4];
            *(float4*)&bwv[4] = *(const float4*)&Bs[kk][64 + tx * 4];
            #pragma unroll
            for (int i = 0; i < 8; i++)
                #pragma unroll
                for (int j = 0; j < 8; j++)
                    acc[i][j] += a[i] * bwv[j];
        }
    }

    #pragma unroll
    for (int i = 0; i < 8; i++) {
        const int row = bm + ((i < 4) ? (ty * 4 + i) : (64 + ty * 4 + (i - 4)));
        float* orow = out + (size_t)row * EE + bn;
        const int c0 = tx * 4;
        float4 r0 = make_float4(acc[i][0] + bias[bn + c0 + 0],
                                acc[i][1] + bias[bn + c0 + 1],
                                acc[i][2] + bias[bn + c0 + 2],
                                acc[i][3] + bias[bn + c0 + 3]);
        float4 r1 = make_float4(acc[i][4] + bias[bn + 64 + c0 + 0],
                                acc[i][5] + bias[bn + 64 + c0 + 1],
                                acc[i][6] + bias[bn + 64 + c0 + 2],
                                acc[i][7] + bias[bn + 64 + c0 + 3]);
        *(float4*)(orow + c0)      = r0;
        *(float4*)(orow + 64 + c0) = r1;
    }
}

// ---------------------------------------------------------------------------
extern "C" void kernel_launch(void* const* d_in, const int* in_sizes, int n_in,
                              void* d_out, int out_size)
{
    const float* q  = (const float*)d_in[0];
    const float* k  = (const float*)d_in[1];
    const float* v  = (const float*)d_in[2];
    const float* qs = (const float*)d_in[3];
    const float* ks = (const float*)d_in[4];
    const float* pw = (const float*)d_in[5];
    const float* pb = (const float*)d_in[6];
    float* out = (float*)d_out;

    prep_kernel<<<BB * NN, 384>>>(q, k, v, qs, ks);
    attn_kernel<<<dim3(NN / BR, BB * HH), BR>>>();
    proj_kernel<<<dim3(EE / 128, (BB * NN) / 128), 256>>>(pw, pb, out);
}

// round 3
// speedup vs baseline: 3.4611x; 3.4611x over previous
#include <cuda_runtime.h>
#include <cuda_bf16.h>

#define BB 4
#define NN 2048
#define EE 768
#define HH 12
#define DD 64
#define RD 32

#define BHND ((size_t)BB * HH * NN * DD)      // 6291456
#define YSZ  ((size_t)BB * NN * EE)           // 6291456

// ---- global scratch (allocation-free contract) ----
__device__ float         g_qh [BHND];
__device__ __nv_bfloat16 g_khi[BHND], g_klo[BHND];
__device__ __nv_bfloat16 g_vhi[BHND], g_vlo[BHND];
__device__ __nv_bfloat16 g_yhi[YSZ],  g_ylo[YSZ];
__device__ __nv_bfloat16 g_whi[EE * EE], g_wlo[EE * EE];

// ---- helpers ----
__device__ __forceinline__ unsigned pack2(__nv_bfloat16 a, __nv_bfloat16 b) {
    __nv_bfloat162 t; t.x = a; t.y = b; return *(unsigned*)&t;
}
__device__ __forceinline__ void splitpack(float2 f, unsigned& hi, unsigned& lo) {
    __nv_bfloat16 hx = __float2bfloat16(f.x), hy = __float2bfloat16(f.y);
    __nv_bfloat16 lx = __float2bfloat16(f.x - __bfloat162float(hx));
    __nv_bfloat16 ly = __float2bfloat16(f.y - __bfloat162float(hy));
    hi = pack2(hx, hy); lo = pack2(lx, ly);
}
__device__ __forceinline__ void mma_bf(float c[4], const unsigned a[4],
                                       unsigned b0, unsigned b1) {
    asm volatile(
        "mma.sync.aligned.m16n8k16.row.col.f32.bf16.bf16.f32 "
        "{%0,%1,%2,%3},{%4,%5,%6,%7},{%8,%9},{%0,%1,%2,%3};\n"
        : "+f"(c[0]), "+f"(c[1]), "+f"(c[2]), "+f"(c[3])
        : "r"(a[0]), "r"(a[1]), "r"(a[2]), "r"(a[3]), "r"(b0), "r"(b1));
}
__device__ __forceinline__ void ldsm4(unsigned& r0, unsigned& r1, unsigned& r2,
                                      unsigned& r3, unsigned addr) {
    asm volatile("ldmatrix.sync.aligned.m8n8.x4.shared.b16 {%0,%1,%2,%3},[%4];\n"
                 : "=r"(r0), "=r"(r1), "=r"(r2), "=r"(r3) : "r"(addr));
}
__device__ __forceinline__ void ldsm4t(unsigned& r0, unsigned& r1, unsigned& r2,
                                       unsigned& r3, unsigned addr) {
    asm volatile("ldmatrix.sync.aligned.m8n8.x4.trans.shared.b16 {%0,%1,%2,%3},[%4];\n"
                 : "=r"(r0), "=r"(r1), "=r"(r2), "=r"(r3) : "r"(addr));
}

// ---------------------------------------------------------------------------
// Kernel 1: RMSNorm + xPos RoPE + head split. Q stays fp32; K/V pre-split to
// bf16 hi/lo planes (split once here instead of per consuming tile).
// ---------------------------------------------------------------------------
__global__ __launch_bounds__(384) void prep_kernel(
    const float* __restrict__ q, const float* __restrict__ k,
    const float* __restrict__ v,
    const float* __restrict__ qs, const float* __restrict__ ks)
{
    const int row = blockIdx.x;
    const int b = row / NN;
    const int n = row - b * NN;
    const int w = threadIdx.x >> 5;
    const int l = threadIdx.x & 31;

    const size_t ibase = (size_t)row * EE + w * DD + 2 * l;
    float x0 = q[ibase], x1 = q[ibase + 1];
    float y0 = k[ibase], y1 = k[ibase + 1];
    float v0 = v[ibase], v1 = v[ibase + 1];

    float sq = x0 * x0 + x1 * x1;
    float sk = y0 * y0 + y1 * y1;
    #pragma unroll
    for (int off = 16; off; off >>= 1) {
        sq += __shfl_xor_sync(0xffffffffu, sq, off);
        sk += __shfl_xor_sync(0xffffffffu, sk, off);
    }
    const float rq = rsqrtf(sq * (1.0f / DD) + 1e-6f);
    const float rk = rsqrtf(sk * (1.0f / DD) + 1e-6f);
    x0 *= rq * qs[2 * l]; x1 *= rq * qs[2 * l + 1];
    y0 *= rk * ks[2 * l]; y1 *= rk * ks[2 * l + 1];

    if (l < 16) {
        const float freq = powf(10000.0f, -(float)l / 16.0f);
        float s, c;
        sincosf((float)n * freq, &s, &c);
        const float base  = (2.0f * l + 0.4f * RD) / (1.4f * RD);
        const float power = ((float)n - (float)(NN / 2)) * (1.0f / 512.0f);
        const float sc  = powf(base,  power);
        const float isc = powf(base, -power);
        const float nx0 = (x0 * c - x1 * s) * sc;
        const float nx1 = (x1 * c + x0 * s) * sc;
        const float ny0 = (y0 * c - y1 * s) * isc;
        const float ny1 = (y1 * c + y0 * s) * isc;
        x0 = nx0; x1 = nx1; y0 = ny0; y1 = ny1;
    }

    const size_t ob = (((size_t)b * HH + w) * NN + n) * DD + 2 * l;
    g_qh[ob] = x0; g_qh[ob + 1] = x1;

    unsigned khi, klo, vhi, vlo;
    splitpack(make_float2(y0, y1), khi, klo);
    splitpack(make_float2(v0, v1), vhi, vlo);
    *(unsigned*)(g_khi + ob) = khi; *(unsigned*)(g_klo + ob) = klo;
    *(unsigned*)(g_vhi + ob) = vhi; *(unsigned*)(g_vlo + ob) = vlo;
}

// ---------------------------------------------------------------------------
// Kernel 1b: split W into bf16 hi/lo once.
// ---------------------------------------------------------------------------
__global__ __launch_bounds__(256) void wsplit_kernel(const float* __restrict__ w)
{
    const int i = blockIdx.x * 256 + threadIdx.x;   // grid sized exactly
    const float f = w[i];
    __nv_bfloat16 h = __float2bfloat16(f);
    g_whi[i] = h;
    g_wlo[i] = __float2bfloat16(f - __bfloat162float(h));
}

// ---------------------------------------------------------------------------
// Kernel 2: causal flash attention, FA2-style mma.sync with split-bf16
// (3-mma Markidis) for both QK^T and PV. BR=128 rows/block, 8 warps x 16
// rows, 64-key tiles. Output written pre-split for the projection GEMM.
// ---------------------------------------------------------------------------
#define BR   128
#define KT   64
#define SROW 72                    // padded bf16 row stride (bank-clean ldmatrix)
#define PLANE (64 * SROW)

__global__ __launch_bounds__(256) void attn_kernel()
{
    __shared__ __align__(16) __nv_bfloat16 smk[2 * PLANE];
    __shared__ __align__(16) __nv_bfloat16 smv[2 * PLANE];

    const int qb   = (int)(gridDim.x - 1 - blockIdx.x);   // heavy-first
    const int bh   = blockIdx.y;
    const int tid  = threadIdx.x;
    const int w    = tid >> 5;
    const int lane = tid & 31;
    const int qr0  = qb * BR + w * 16 + (lane >> 2);
    const int qr1  = qr0 + 8;
    const int c2   = (lane & 3) * 2;

    const size_t hb = (size_t)bh * NN * DD;
    const float* __restrict__ Q = g_qh + hb;

    // Q fragments (A operand), split hi/lo, all 4 k-chunks
    unsigned qhi[4][4], qlo[4][4];
    #pragma unroll
    for (int kc = 0; kc < 4; kc++) {
        const int c0 = kc * 16 + c2;
        splitpack(*(const float2*)(Q + (size_t)qr0 * DD + c0),     qhi[kc][0], qlo[kc][0]);
        splitpack(*(const float2*)(Q + (size_t)qr1 * DD + c0),     qhi[kc][1], qlo[kc][1]);
        splitpack(*(const float2*)(Q + (size_t)qr0 * DD + c0 + 8), qhi[kc][2], qlo[kc][2]);
        splitpack(*(const float2*)(Q + (size_t)qr1 * DD + c0 + 8), qhi[kc][3], qlo[kc][3]);
    }

    float oacc[8][4];
    #pragma unroll
    for (int i = 0; i < 8; i++)
        #pragma unroll
        for (int jj = 0; jj < 4; jj++) oacc[i][jj] = 0.f;
    float mA = -1e30f, mB = -1e30f, lA = 0.f, lB = 0.f;

    const unsigned skb = (unsigned)__cvta_generic_to_shared(smk);
    const unsigned svb = (unsigned)__cvta_generic_to_shared(smv);
    const int pl = lane >> 4;
    // K (B operand, no-trans): matrix rows = keys, cols = d
    const unsigned kbase = skb + (unsigned)(pl * PLANE + (lane & 7) * SROW +
                                            ((lane & 8) ? 8 : 0)) * 2;
    // V (B operand, trans): rows = keys, cols = d
    const unsigned vbase = svb + (unsigned)(pl * PLANE + (lane & 15) * SROW) * 2;

    const int wrow_max = qb * BR + w * 16 + 15;
    const int jmax = 2 * qb + 1;

    for (int j = 0; j <= jmax; j++) {
        const int kb = j * KT;
        __syncthreads();
        {   // 64 rows x 8 uint4 per plane = 512 uint4; 4 planes
            const uint4* gk0 = (const uint4*)(g_khi + hb + (size_t)kb * DD);
            const uint4* gk1 = (const uint4*)(g_klo + hb + (size_t)kb * DD);
            const uint4* gv0 = (const uint4*)(g_vhi + hb + (size_t)kb * DD);
            const uint4* gv1 = (const uint4*)(g_vlo + hb + (size_t)kb * DD);
            #pragma unroll
            for (int p = 0; p < 2; p++) {
                const int i   = tid + p * 256;
                const int row = i >> 3;
                const int cc  = (i & 7) * 8;
                *(uint4*)(smk + row * SROW + cc)         = gk0[i];
                *(uint4*)(smk + PLANE + row * SROW + cc) = gk1[i];
                *(uint4*)(smv + row * SROW + cc)         = gv0[i];
                *(uint4*)(smv + PLANE + row * SROW + cc) = gv1[i];
            }
        }
        __syncthreads();
        if (kb > wrow_max) continue;       // tile entirely above diagonal

        // ---- S = Q K^T ----
        float sacc[8][4];
        #pragma unroll
        for (int nt = 0; nt < 8; nt++)
            #pragma unroll
            for (int i = 0; i < 4; i++) sacc[nt][i] = 0.f;

        #pragma unroll
        for (int kc = 0; kc < 4; kc++) {
            #pragma unroll
            for (int nt = 0; nt < 8; nt++) {
                unsigned r0, r1, r2, r3;
                ldsm4(r0, r1, r2, r3,
                      kbase + (unsigned)(nt * 8 * SROW * 2 + kc * 32));
                mma_bf(sacc[nt], qhi[kc], r0, r1);   // hi*hi
                mma_bf(sacc[nt], qhi[kc], r2, r3);   // hi*lo
                mma_bf(sacc[nt], qlo[kc], r0, r1);   // lo*hi
            }
        }

        // ---- softmax (online) ----
        const bool mk0 = (kb + 63 > qr0);
        float mtA = -1e30f, mtB = -1e30f;
        #pragma unroll
        for (int nt = 0; nt < 8; nt++) {
            float s0 = sacc[nt][0] * 0.125f, s1 = sacc[nt][1] * 0.125f;
            float s2 = sacc[nt][2] * 0.125f, s3 = sacc[nt][3] * 0.125f;
            if (mk0) {
                const int col = kb + nt * 8 + c2;
                if (col     > qr0) s0 = -1e30f;
                if (col + 1 > qr0) s1 = -1e30f;
                if (col     > qr1) s2 = -1e30f;
                if (col + 1 > qr1) s3 = -1e30f;
            }
            sacc[nt][0] = s0; sacc[nt][1] = s1; sacc[nt][2] = s2; sacc[nt][3] = s3;
            mtA = fmaxf(mtA, fmaxf(s0, s1));
            mtB = fmaxf(mtB, fmaxf(s2, s3));
        }
        mtA = fmaxf(mtA, __shfl_xor_sync(0xffffffffu, mtA, 1));
        mtA = fmaxf(mtA, __shfl_xor_sync(0xffffffffu, mtA, 2));
        mtB = fmaxf(mtB, __shfl_xor_sync(0xffffffffu, mtB, 1));
        mtB = fmaxf(mtB, __shfl_xor_sync(0xffffffffu, mtB, 2));
        const float mnA = fmaxf(mA, mtA), mnB = fmaxf(mB, mtB);
        const float aA = __expf(mA - mnA), aB = __expf(mB - mnB);
        mA = mnA; mB = mnB;
        lA *= aA; lB *= aB;
        #pragma unroll
        for (int dt = 0; dt < 8; dt++) {
            oacc[dt][0] *= aA; oacc[dt][1] *= aA;
            oacc[dt][2] *= aB; oacc[dt][3] *= aB;
        }
        #pragma unroll
        for (int nt = 0; nt < 8; nt++) {
            const float p0 = __expf(sacc[nt][0] - mnA);
            const float p1 = __expf(sacc[nt][1] - mnA);
            const float p2 = __expf(sacc[nt][2] - mnB);
            const float p3 = __expf(sacc[nt][3] - mnB);
            lA += p0 + p1; lB += p2 + p3;
            sacc[nt][0] = p0; sacc[nt][1] = p1; sacc[nt][2] = p2; sacc[nt][3] = p3;
        }

        // ---- O += P V ----
        #pragma unroll
        for (int kc = 0; kc < 4; kc++) {
            unsigned phi[4], plo2[4];
            splitpack(make_float2(sacc[2*kc][0],   sacc[2*kc][1]),   phi[0], plo2[0]);
            splitpack(make_float2(sacc[2*kc][2],   sacc[2*kc][3]),   phi[1], plo2[1]);
            splitpack(make_float2(sacc[2*kc+1][0], sacc[2*kc+1][1]), phi[2], plo2[2]);
            splitpack(make_float2(sacc[2*kc+1][2], sacc[2*kc+1][3]), phi[3], plo2[3]);
            #pragma unroll
            for (int dt = 0; dt < 8; dt++) {
                unsigned r0, r1, r2, r3;
                ldsm4t(r0, r1, r2, r3,
                       vbase + (unsigned)(kc * 16 * SROW * 2 + dt * 16));
                mma_bf(oacc[dt], phi, r0, r1);    // hi*hi
                mma_bf(oacc[dt], phi, r2, r3);    // hi*lo
                mma_bf(oacc[dt], plo2, r0, r1);   // lo*hi
            }
        }
    }

    // finalize: row-sum across the quad, normalize, split-store y
    lA += __shfl_xor_sync(0xffffffffu, lA, 1);
    lA += __shfl_xor_sync(0xffffffffu, lA, 2);
    lB += __shfl_xor_sync(0xffffffffu, lB, 1);
    lB += __shfl_xor_sync(0xffffffffu, lB, 2);
    const float iA = __fdividef(1.0f, lA);
    const float iB = __fdividef(1.0f, lB);

    const int b = bh / HH, h = bh - b * HH;
    const size_t r0b = ((size_t)b * NN + qr0) * EE + h * DD;
    const size_t r1b = ((size_t)b * NN + qr1) * EE + h * DD;
    #pragma unroll
    for (int dt = 0; dt < 8; dt++) {
        const int col = dt * 8 + c2;
        unsigned hi, lo;
        splitpack(make_float2(oacc[dt][0] * iA, oacc[dt][1] * iA), hi, lo);
        *(unsigned*)(g_yhi + r0b + col) = hi;
        *(unsigned*)(g_ylo + r0b + col) = lo;
        splitpack(make_float2(oacc[dt][2] * iB, oacc[dt][3] * iB), hi, lo);
        *(unsigned*)(g_yhi + r1b + col) = hi;
        *(unsigned*)(g_ylo + r1b + col) = lo;
    }
}

// ---------------------------------------------------------------------------
// Kernel 3: out = Y W^T + b via split-bf16 mma. 128x128 tile, 8 warps (2x4),
// k-stage of 32.
// ---------------------------------------------------------------------------
#define PROW  40
#define APLANE (128 * PROW)

__global__ __launch_bounds__(256) void proj_kernel(
    const float* __restrict__ bias, float* __restrict__ out)
{
    __shared__ __align__(16) __nv_bfloat16 sA[2 * APLANE];
    __shared__ __align__(16) __nv_bfloat16 sB[2 * APLANE];

    const int tid = threadIdx.x, w = tid >> 5, lane = tid & 31;
    const int bm = blockIdx.y * 128, bn = blockIdx.x * 128;
    const int wm = w >> 2, wn = w & 3;

    float acc[4][4][4];
    #pragma unroll
    for (int a = 0; a < 4; a++)
        #pragma unroll
        for (int b2 = 0; b2 < 4; b2++)
            #pragma unroll
            for (int c = 0; c < 4; c++) acc[a][b2][c] = 0.f;

    const unsigned sab = (unsigned)__cvta_generic_to_shared(sA);
    const unsigned sbb = (unsigned)__cvta_generic_to_shared(sB);
    // A frag (16x16, no-trans): lanes 0-15 rows, lanes 16-31 col+8
    const unsigned abase = sab + (unsigned)((wm * 64 + (lane & 15)) * PROW +
                                            ((lane & 16) ? 8 : 0)) * 2;
    // B frag x4 (hi+lo): lanes 0-7 rows@c, 8-15 rows@c+8, 16-31 lo plane
    const unsigned bbase = sbb + (unsigned)((lane >> 4) * APLANE +
                                            (wn * 32 + (lane & 7)) * PROW +
                                            ((lane & 8) ? 8 : 0)) * 2;

    for (int k0 = 0; k0 < EE; k0 += 32) {
        __syncthreads();
        #pragma unroll
        for (int p = 0; p < 8; p++) {
            const int i = tid + p * 256;        // 0..2047
            const int plane = i >> 9;           // 0:Ahi 1:Alo 2:Bhi 3:Blo
            const int rem = i & 511;
            const int row = rem >> 2;
            const int cc  = (rem & 3) * 8;
            const __nv_bfloat16* src;
            __nv_bfloat16* dst;
            if (plane == 0) {
                src = g_yhi + (size_t)(bm + row) * EE + k0 + cc;
                dst = sA + row * PROW + cc;
            } else if (plane == 1) {
                src = g_ylo + (size_t)(bm + row) * EE + k0 + cc;
                dst = sA + APLANE + row * PROW + cc;
            } else if (plane == 2) {
                src = g_whi + (size_t)(bn + row) * EE + k0 + cc;
                dst = sB + row * PROW + cc;
            } else {
                src = g_wlo + (size_t)(bn + row) * EE + k0 + cc;
                dst = sB + APLANE + row * PROW + cc;
            }
            *(uint4*)dst = *(const uint4*)src;
        }
        __syncthreads();

        #pragma unroll
        for (int kc = 0; kc < 2; kc++) {
            unsigned ahi[4][4], alo[4][4];
            #pragma unroll
            for (int mi = 0; mi < 4; mi++) {
                ldsm4(ahi[mi][0], ahi[mi][1], ahi[mi][2], ahi[mi][3],
                      abase + (unsigned)(mi * 16 * PROW * 2 + kc * 32));
                ldsm4(alo[mi][0], alo[mi][1], alo[mi][2], alo[mi][3],
                      abase + (unsigned)(APLANE * 2 + mi * 16 * PROW * 2 + kc * 32));
            }
            #pragma unroll
            for (int ni = 0; ni < 4; ni++) {
                unsigned r0, r1, r2, r3;
                ldsm4(r0, r1, r2, r3,
                      bbase + (unsigned)(ni * 8 * PROW * 2 + kc * 32));
                #pragma unroll
                for (int mi = 0; mi < 4; mi++) {
                    mma_bf(acc[mi][ni], ahi[mi], r0, r1);  // hi*hi
                    mma_bf(acc[mi][ni], ahi[mi], r2, r3);  // hi*lo
                    mma_bf(acc[mi][ni], alo[mi], r0, r1);  // lo*hi
                }
            }
        }
    }

    const int rA = bm + wm * 64 + (lane >> 2);
    #pragma unroll
    for (int mi = 0; mi < 4; mi++) {
        const int r0 = rA + mi * 16, r1 = r0 + 8;
        #pragma unroll
        for (int ni = 0; ni < 4; ni++) {
            const int col = bn + wn * 32 + ni * 8 + (lane & 3) * 2;
            const float b0 = bias[col], b1 = bias[col + 1];
            *(float2*)(out + (size_t)r0 * EE + col) =
                make_float2(acc[mi][ni][0] + b0, acc[mi][ni][1] + b1);
            *(float2*)(out + (size_t)r1 * EE + col) =
                make_float2(acc[mi][ni][2] + b0, acc[mi][ni][3] + b1);
        }
    }
}

// ---------------------------------------------------------------------------
extern "C" void kernel_launch(void* const* d_in, const int* in_sizes, int n_in,
                              void* d_out, int out_size)
{
    const float* q  = (const float*)d_in[0];
    const float* k  = (const float*)d_in[1];
    const float* v  = (const float*)d_in[2];
    const float* qs = (const float*)d_in[3];
    const float* ks = (const float*)d_in[4];
    const float* pw = (const float*)d_in[5];
    const float* pb = (const float*)d_in[6];
    float* out = (float*)d_out;

    prep_kernel<<<BB * NN, 384>>>(q, k, v, qs, ks);
    wsplit_kernel<<<(EE * EE) / 256, 256>>>(pw);
    attn_kernel<<<dim3(NN / BR, BB * HH), 256>>>();
    proj_kernel<<<dim3(EE / 128, (BB * NN) / 128), 256>>>(pb, out);
}

// round 7
// speedup vs baseline: 4.2178x; 1.2186x over previous
#include <cuda_runtime.h>
#include <cuda_bf16.h>

#define BB 4
#define NN 2048
#define EE 768
#define HH 12
#define DD 64
#define RD 32

#define BHND ((size_t)BB * HH * NN * DD)      // 6291456
#define YSZ  ((size_t)BB * NN * EE)           // 6291456

// ---- global scratch (allocation-free contract) ----
__device__ float         g_qh [BHND];
__device__ __nv_bfloat16 g_khi[BHND], g_klo[BHND];
__device__ __nv_bfloat16 g_vhi[BHND], g_vlo[BHND];
__device__ __nv_bfloat16 g_yhi[YSZ],  g_ylo[YSZ];
__device__ __nv_bfloat16 g_whi[EE * EE], g_wlo[EE * EE];

// ---- helpers ----
__device__ __forceinline__ unsigned pack2(__nv_bfloat16 a, __nv_bfloat16 b) {
    __nv_bfloat162 t; t.x = a; t.y = b; return *(unsigned*)&t;
}
__device__ __forceinline__ void splitpack(float2 f, unsigned& hi, unsigned& lo) {
    __nv_bfloat16 hx = __float2bfloat16(f.x), hy = __float2bfloat16(f.y);
    __nv_bfloat16 lx = __float2bfloat16(f.x - __bfloat162float(hx));
    __nv_bfloat16 ly = __float2bfloat16(f.y - __bfloat162float(hy));
    hi = pack2(hx, hy); lo = pack2(lx, ly);
}
__device__ __forceinline__ void mma_bf(float c[4], const unsigned a[4],
                                       unsigned b0, unsigned b1) {
    asm volatile(
        "mma.sync.aligned.m16n8k16.row.col.f32.bf16.bf16.f32 "
        "{%0,%1,%2,%3},{%4,%5,%6,%7},{%8,%9},{%0,%1,%2,%3};\n"
        : "+f"(c[0]), "+f"(c[1]), "+f"(c[2]), "+f"(c[3])
        : "r"(a[0]), "r"(a[1]), "r"(a[2]), "r"(a[3]), "r"(b0), "r"(b1));
}
__device__ __forceinline__ void ldsm4(unsigned& r0, unsigned& r1, unsigned& r2,
                                      unsigned& r3, unsigned addr) {
    asm volatile("ldmatrix.sync.aligned.m8n8.x4.shared.b16 {%0,%1,%2,%3},[%4];\n"
                 : "=r"(r0), "=r"(r1), "=r"(r2), "=r"(r3) : "r"(addr));
}
__device__ __forceinline__ void ldsm4t(unsigned& r0, unsigned& r1, unsigned& r2,
                                       unsigned& r3, unsigned addr) {
    asm volatile("ldmatrix.sync.aligned.m8n8.x4.trans.shared.b16 {%0,%1,%2,%3},[%4];\n"
                 : "=r"(r0), "=r"(r1), "=r"(r2), "=r"(r3) : "r"(addr));
}
__device__ __forceinline__ void cpa16(unsigned dst, const void* src) {
    asm volatile("cp.async.cg.shared.global [%0], [%1], 16;\n"
                 :: "r"(dst), "l"(src));
}
__device__ __forceinline__ void cpcommit() {
    asm volatile("cp.async.commit_group;\n");
}
template <int N> __device__ __forceinline__ void cpwait() {
    asm volatile("cp.async.wait_group %0;\n" :: "n"(N));
}

// ---------------------------------------------------------------------------
// Kernel 1: RMSNorm + xPos RoPE + head split. Q stays fp32; K/V pre-split to
// bf16 hi/lo planes.
// ---------------------------------------------------------------------------
__global__ __launch_bounds__(384) void prep_kernel(
    const float* __restrict__ q, const float* __restrict__ k,
    const float* __restrict__ v,
    const float* __restrict__ qs, const float* __restrict__ ks)
{
    const int row = blockIdx.x;
    const int b = row / NN;
    const int n = row - b * NN;
    const int w = threadIdx.x >> 5;
    const int l = threadIdx.x & 31;

    const size_t ibase = (size_t)row * EE + w * DD + 2 * l;
    float x0 = q[ibase], x1 = q[ibase + 1];
    float y0 = k[ibase], y1 = k[ibase + 1];
    float v0 = v[ibase], v1 = v[ibase + 1];

    float sq = x0 * x0 + x1 * x1;
    float sk = y0 * y0 + y1 * y1;
    #pragma unroll
    for (int off = 16; off; off >>= 1) {
        sq += __shfl_xor_sync(0xffffffffu, sq, off);
        sk += __shfl_xor_sync(0xffffffffu, sk, off);
    }
    const float rq = rsqrtf(sq * (1.0f / DD) + 1e-6f);
    const float rk = rsqrtf(sk * (1.0f / DD) + 1e-6f);
    x0 *= rq * qs[2 * l]; x1 *= rq * qs[2 * l + 1];
    y0 *= rk * ks[2 * l]; y1 *= rk * ks[2 * l + 1];

    if (l < 16) {
        const float freq = powf(10000.0f, -(float)l / 16.0f);
        float s, c;
        sincosf((float)n * freq, &s, &c);
        const float base  = (2.0f * l + 0.4f * RD) / (1.4f * RD);
        const float power = ((float)n - (float)(NN / 2)) * (1.0f / 512.0f);
        const float sc  = powf(base,  power);
        const float isc = powf(base, -power);
        const float nx0 = (x0 * c - x1 * s) * sc;
        const float nx1 = (x1 * c + x0 * s) * sc;
        const float ny0 = (y0 * c - y1 * s) * isc;
        const float ny1 = (y1 * c + y0 * s) * isc;
        x0 = nx0; x1 = nx1; y0 = ny0; y1 = ny1;
    }

    const size_t ob = (((size_t)b * HH + w) * NN + n) * DD + 2 * l;
    g_qh[ob] = x0; g_qh[ob + 1] = x1;

    unsigned khi, klo, vhi, vlo;
    splitpack(make_float2(y0, y1), khi, klo);
    splitpack(make_float2(v0, v1), vhi, vlo);
    *(unsigned*)(g_khi + ob) = khi; *(unsigned*)(g_klo + ob) = klo;
    *(unsigned*)(g_vhi + ob) = vhi; *(unsigned*)(g_vlo + ob) = vlo;
}

// ---------------------------------------------------------------------------
// Kernel 1b: split W into bf16 hi/lo once.
// ---------------------------------------------------------------------------
__global__ __launch_bounds__(256) void wsplit_kernel(const float* __restrict__ w)
{
    const int i = blockIdx.x * 256 + threadIdx.x;
    const float f = w[i];
    __nv_bfloat16 h = __float2bfloat16(f);
    g_whi[i] = h;
    g_wlo[i] = __float2bfloat16(f - __bfloat162float(h));
}

// ---------------------------------------------------------------------------
// Kernel 2: causal flash attention, split-bf16 mma, cp.async double-buffered
// K/V tiles (2 stages). Dynamic smem: 2 stages x (Khi,Klo,Vhi,Vlo) planes.
// ---------------------------------------------------------------------------
#define BR   128
#define KT   64
#define SROW 72
#define PLANE (64 * SROW)                 // elems per plane
#define STAGE_B (4 * PLANE)               // bytes per K (or V) stage (2 planes)

__global__ __launch_bounds__(256, 1) void attn_kernel()
{
    extern __shared__ __nv_bfloat16 dynsm_a[];
    __nv_bfloat16* smk = dynsm_a;                 // [2 stages][2 planes][PLANE]
    __nv_bfloat16* smv = dynsm_a + 4 * PLANE;

    const int qb   = (int)(gridDim.x - 1 - blockIdx.x);
    const int bh   = blockIdx.y;
    const int tid  = threadIdx.x;
    const int w    = tid >> 5;
    const int lane = tid & 31;
    const int qr0  = qb * BR + w * 16 + (lane >> 2);
    const int qr1  = qr0 + 8;
    const int c2   = (lane & 3) * 2;

    const size_t hb = (size_t)bh * NN * DD;
    const float* __restrict__ Q = g_qh + hb;

    unsigned qhi[4][4], qlo[4][4];
    #pragma unroll
    for (int kc = 0; kc < 4; kc++) {
        const int c0 = kc * 16 + c2;
        splitpack(*(const float2*)(Q + (size_t)qr0 * DD + c0),     qhi[kc][0], qlo[kc][0]);
        splitpack(*(const float2*)(Q + (size_t)qr1 * DD + c0),     qhi[kc][1], qlo[kc][1]);
        splitpack(*(const float2*)(Q + (size_t)qr0 * DD + c0 + 8), qhi[kc][2], qlo[kc][2]);
        splitpack(*(const float2*)(Q + (size_t)qr1 * DD + c0 + 8), qhi[kc][3], qlo[kc][3]);
    }

    float oacc[8][4];
    #pragma unroll
    for (int i = 0; i < 8; i++)
        #pragma unroll
        for (int jj = 0; jj < 4; jj++) oacc[i][jj] = 0.f;
    float mA = -1e30f, mB = -1e30f, lA = 0.f, lB = 0.f;

    const unsigned skb = (unsigned)__cvta_generic_to_shared(smk);
    const unsigned svb = (unsigned)__cvta_generic_to_shared(smv);
    const int pl = lane >> 4;
    const unsigned kbase0 = skb + (unsigned)(pl * PLANE + (lane & 7) * SROW +
                                             ((lane & 8) ? 8 : 0)) * 2;
    const unsigned vbase0 = svb + (unsigned)(pl * PLANE + (lane & 15) * SROW) * 2;

    // per-thread loader slots: i = tid + p*256, row=i>>3, cc=(i&7)*8
    const int l_row = tid >> 3;
    const int l_cc  = (tid & 7) * 8;
    const unsigned l_off0 = (unsigned)(l_row * SROW + l_cc) * 2;
    const unsigned l_off1 = (unsigned)((l_row + 32) * SROW + l_cc) * 2;
    const size_t g_off0 = (size_t)l_row * DD + l_cc;
    const size_t g_off1 = (size_t)(l_row + 32) * DD + l_cc;

    const int wrow_max = qb * BR + w * 16 + 15;
    const int jmax = 2 * qb + 1;

    // ---- prefetch tile 0 into stage 0 ----
    {
        const size_t tb = hb;             // kb = 0
        const unsigned sk0 = skb, sv0 = svb;
        cpa16(sk0 + l_off0,             g_khi + tb + g_off0);
        cpa16(sk0 + l_off1,             g_khi + tb + g_off1);
        cpa16(sk0 + PLANE * 2 + l_off0, g_klo + tb + g_off0);
        cpa16(sk0 + PLANE * 2 + l_off1, g_klo + tb + g_off1);
        cpa16(sv0 + l_off0,             g_vhi + tb + g_off0);
        cpa16(sv0 + l_off1,             g_vhi + tb + g_off1);
        cpa16(sv0 + PLANE * 2 + l_off0, g_vlo + tb + g_off0);
        cpa16(sv0 + PLANE * 2 + l_off1, g_vlo + tb + g_off1);
        cpcommit();
    }

    for (int j = 0; j <= jmax; j++) {
        const int kb  = j * KT;
        const int cur = j & 1;

        if (j < jmax) {                   // prefetch tile j+1 into other stage
            const size_t tb = hb + (size_t)(kb + KT) * DD;
            const unsigned sb = (unsigned)((cur ^ 1) * STAGE_B);
            const unsigned sk1 = skb + sb, sv1 = svb + sb;
            cpa16(sk1 + l_off0,             g_khi + tb + g_off0);
            cpa16(sk1 + l_off1,             g_khi + tb + g_off1);
            cpa16(sk1 + PLANE * 2 + l_off0, g_klo + tb + g_off0);
            cpa16(sk1 + PLANE * 2 + l_off1, g_klo + tb + g_off1);
            cpa16(sv1 + l_off0,             g_vhi + tb + g_off0);
            cpa16(sv1 + l_off1,             g_vhi + tb + g_off1);
            cpa16(sv1 + PLANE * 2 + l_off0, g_vlo + tb + g_off0);
            cpa16(sv1 + PLANE * 2 + l_off1, g_vlo + tb + g_off1);
            cpcommit();
            cpwait<1>();
        } else {
            cpwait<0>();
        }
        __syncthreads();                  // tile j visible to all warps

        if (kb <= wrow_max) {
            const unsigned kbase = kbase0 + (unsigned)(cur * STAGE_B);
            const unsigned vbase = vbase0 + (unsigned)(cur * STAGE_B);

            // ---- S = Q K^T ----
            float sacc[8][4];
            #pragma unroll
            for (int nt = 0; nt < 8; nt++)
                #pragma unroll
                for (int i = 0; i < 4; i++) sacc[nt][i] = 0.f;

            #pragma unroll
            for (int kc = 0; kc < 4; kc++) {
                #pragma unroll
                for (int nt = 0; nt < 8; nt++) {
                    unsigned r0, r1, r2, r3;
                    ldsm4(r0, r1, r2, r3,
                          kbase + (unsigned)(nt * 8 * SROW * 2 + kc * 32));
                    mma_bf(sacc[nt], qhi[kc], r0, r1);
                    mma_bf(sacc[nt], qhi[kc], r2, r3);
                    mma_bf(sacc[nt], qlo[kc], r0, r1);
                }
            }

            // ---- online softmax ----
            const bool mk0 = (kb + 63 > qr0);
            float mtA = -1e30f, mtB = -1e30f;
            #pragma unroll
            for (int nt = 0; nt < 8; nt++) {
                float s0 = sacc[nt][0] * 0.125f, s1 = sacc[nt][1] * 0.125f;
                float s2 = sacc[nt][2] * 0.125f, s3 = sacc[nt][3] * 0.125f;
                if (mk0) {
                    const int col = kb + nt * 8 + c2;
                    if (col     > qr0) s0 = -1e30f;
                    if (col + 1 > qr0) s1 = -1e30f;
                    if (col     > qr1) s2 = -1e30f;
                    if (col + 1 > qr1) s3 = -1e30f;
                }
                sacc[nt][0] = s0; sacc[nt][1] = s1;
                sacc[nt][2] = s2; sacc[nt][3] = s3;
                mtA = fmaxf(mtA, fmaxf(s0, s1));
                mtB = fmaxf(mtB, fmaxf(s2, s3));
            }
            mtA = fmaxf(mtA, __shfl_xor_sync(0xffffffffu, mtA, 1));
            mtA = fmaxf(mtA, __shfl_xor_sync(0xffffffffu, mtA, 2));
            mtB = fmaxf(mtB, __shfl_xor_sync(0xffffffffu, mtB, 1));
            mtB = fmaxf(mtB, __shfl_xor_sync(0xffffffffu, mtB, 2));
            const float mnA = fmaxf(mA, mtA), mnB = fmaxf(mB, mtB);
            const float aA = __expf(mA - mnA), aB = __expf(mB - mnB);
            mA = mnA; mB = mnB;
            lA *= aA; lB *= aB;
            #pragma unroll
            for (int dt = 0; dt < 8; dt++) {
                oacc[dt][0] *= aA; oacc[dt][1] *= aA;
                oacc[dt][2] *= aB; oacc[dt][3] *= aB;
            }
            #pragma unroll
            for (int nt = 0; nt < 8; nt++) {
                const float p0 = __expf(sacc[nt][0] - mnA);
                const float p1 = __expf(sacc[nt][1] - mnA);
                const float p2 = __expf(sacc[nt][2] - mnB);
                const float p3 = __expf(sacc[nt][3] - mnB);
                lA += p0 + p1; lB += p2 + p3;
                sacc[nt][0] = p0; sacc[nt][1] = p1;
                sacc[nt][2] = p2; sacc[nt][3] = p3;
            }

            // ---- O += P V ----
            #pragma unroll
            for (int kc = 0; kc < 4; kc++) {
                unsigned phi[4], plo2[4];
                splitpack(make_float2(sacc[2*kc][0],   sacc[2*kc][1]),   phi[0], plo2[0]);
                splitpack(make_float2(sacc[2*kc][2],   sacc[2*kc][3]),   phi[1], plo2[1]);
                splitpack(make_float2(sacc[2*kc+1][0], sacc[2*kc+1][1]), phi[2], plo2[2]);
                splitpack(make_float2(sacc[2*kc+1][2], sacc[2*kc+1][3]), phi[3], plo2[3]);
                #pragma unroll
                for (int dt = 0; dt < 8; dt++) {
                    unsigned r0, r1, r2, r3;
                    ldsm4t(r0, r1, r2, r3,
                           vbase + (unsigned)(kc * 16 * SROW * 2 + dt * 16));
                    mma_bf(oacc[dt], phi,  r0, r1);
                    mma_bf(oacc[dt], phi,  r2, r3);
                    mma_bf(oacc[dt], plo2, r0, r1);
                }
            }
        }
        __syncthreads();                  // all done with stage cur before overwrite
    }

    lA += __shfl_xor_sync(0xffffffffu, lA, 1);
    lA += __shfl_xor_sync(0xffffffffu, lA, 2);
    lB += __shfl_xor_sync(0xffffffffu, lB, 1);
    lB += __shfl_xor_sync(0xffffffffu, lB, 2);
    const float iA = __fdividef(1.0f, lA);
    const float iB = __fdividef(1.0f, lB);

    const int b = bh / HH, h = bh - b * HH;
    const size_t r0b = ((size_t)b * NN + qr0) * EE + h * DD;
    const size_t r1b = ((size_t)b * NN + qr1) * EE + h * DD;
    #pragma unroll
    for (int dt = 0; dt < 8; dt++) {
        const int col = dt * 8 + c2;
        unsigned hi, lo;
        splitpack(make_float2(oacc[dt][0] * iA, oacc[dt][1] * iA), hi, lo);
        *(unsigned*)(g_yhi + r0b + col) = hi;
        *(unsigned*)(g_ylo + r0b + col) = lo;
        splitpack(make_float2(oacc[dt][2] * iB, oacc[dt][3] * iB), hi, lo);
        *(unsigned*)(g_yhi + r1b + col) = hi;
        *(unsigned*)(g_ylo + r1b + col) = lo;
    }
}

// ---------------------------------------------------------------------------
// Kernel 3: out = Y W^T + b, split-bf16 mma, cp.async double-buffered k-stages.
// ---------------------------------------------------------------------------
#define PROW   40
#define APLANE (128 * PROW)               // elems per plane
#define PSTG_B (4 * APLANE)               // bytes per stage (2 planes)
#define NKIT   (EE / 32)                  // 24 k-stages

__global__ __launch_bounds__(256, 2) void proj_kernel(
    const float* __restrict__ bias, float* __restrict__ out)
{
    extern __shared__ __nv_bfloat16 dynsm_p[];
    __nv_bfloat16* sA = dynsm_p;                  // [2 stages][hi,lo][APLANE]
    __nv_bfloat16* sB = dynsm_p + 4 * APLANE;

    const int tid = threadIdx.x, w = tid >> 5, lane = tid & 31;
    const int bm = blockIdx.y * 128, bn = blockIdx.x * 128;
    const int wm = w >> 2, wn = w & 3;

    float acc[4][4][4];
    #pragma unroll
    for (int a = 0; a < 4; a++)
        #pragma unroll
        for (int b2 = 0; b2 < 4; b2++)
            #pragma unroll
            for (int c = 0; c < 4; c++) acc[a][b2][c] = 0.f;

    const unsigned sab = (unsigned)__cvta_generic_to_shared(sA);
    const unsigned sbb = (unsigned)__cvta_generic_to_shared(sB);
    const unsigned abase0 = sab + (unsigned)((wm * 64 + (lane & 15)) * PROW +
                                             ((lane & 16) ? 8 : 0)) * 2;
    const unsigned bbase0 = sbb + (unsigned)((lane >> 4) * APLANE +
                                             (wn * 32 + (lane & 7)) * PROW +
                                             ((lane & 8) ? 8 : 0)) * 2;

    // loader: i = tid + p*256, p=0..7; plane = i>>9 (0:Ahi 1:Alo 2:Bhi 3:Blo)
    // rem = i&511, row = rem>>2, cc = (rem&3)*8
    auto load_stage = [&](int stage, int k0) {
        const unsigned sb = (unsigned)(stage * PSTG_B);
        #pragma unroll
        for (int p = 0; p < 8; p++) {
            const int i = tid + p * 256;
            const int plane = i >> 9;
            const int rem = i & 511;
            const int row = rem >> 2;
            const int cc  = (rem & 3) * 8;
            const unsigned doff = sb + (unsigned)((plane & 1) * APLANE +
                                                  row * PROW + cc) * 2;
            if (plane == 0)
                cpa16(sab + doff, g_yhi + (size_t)(bm + row) * EE + k0 + cc);
            else if (plane == 1)
                cpa16(sab + doff, g_ylo + (size_t)(bm + row) * EE + k0 + cc);
            else if (plane == 2)
                cpa16(sbb + doff, g_whi + (size_t)(bn + row) * EE + k0 + cc);
            else
                cpa16(sbb + doff, g_wlo + (size_t)(bn + row) * EE + k0 + cc);
        }
        cpcommit();
    };

    load_stage(0, 0);

    for (int it = 0; it < NKIT; it++) {
        const int cur = it & 1;
        if (it < NKIT - 1) { load_stage(cur ^ 1, (it + 1) * 32); cpwait<1>(); }
        else               { cpwait<0>(); }
        __syncthreads();

        const unsigned abase = abase0 + (unsigned)(cur * PSTG_B);
        const unsigned bbase = bbase0 + (unsigned)(cur * PSTG_B);

        #pragma unroll
        for (int kc = 0; kc < 2; kc++) {
            unsigned ahi[4][4], alo[4][4];
            #pragma unroll
            for (int mi = 0; mi < 4; mi++) {
                ldsm4(ahi[mi][0], ahi[mi][1], ahi[mi][2], ahi[mi][3],
                      abase + (unsigned)(mi * 16 * PROW * 2 + kc * 32));
                ldsm4(alo[mi][0], alo[mi][1], alo[mi][2], alo[mi][3],
                      abase + (unsigned)(APLANE * 2 + mi * 16 * PROW * 2 + kc * 32));
            }
            #pragma unroll
            for (int ni = 0; ni < 4; ni++) {
                unsigned r0, r1, r2, r3;
                ldsm4(r0, r1, r2, r3,
                      bbase + (unsigned)(ni * 8 * PROW * 2 + kc * 32));
                #pragma unroll
                for (int mi = 0; mi < 4; mi++) {
                    mma_bf(acc[mi][ni], ahi[mi], r0, r1);
                    mma_bf(acc[mi][ni], ahi[mi], r2, r3);
                    mma_bf(acc[mi][ni], alo[mi], r0, r1);
                }
            }
        }
        __syncthreads();
    }

    const int rA = bm + wm * 64 + (lane >> 2);
    #pragma unroll
    for (int mi = 0; mi < 4; mi++) {
        const int r0 = rA + mi * 16, r1 = r0 + 8;
        #pragma unroll
        for (int ni = 0; ni < 4; ni++) {
            const int col = bn + wn * 32 + ni * 8 + (lane & 3) * 2;
            const float b0 = bias[col], b1 = bias[col + 1];
            *(float2*)(out + (size_t)r0 * EE + col) =
                make_float2(acc[mi][ni][0] + b0, acc[mi][ni][1] + b1);
            *(float2*)(out + (size_t)r1 * EE + col) =
                make_float2(acc[mi][ni][2] + b0, acc[mi][ni][3] + b1);
        }
    }
}

#define ATTN_SMEM (8 * PLANE * 2)         // 73728 bytes
#define PROJ_SMEM (8 * APLANE * 2)        // 81920 bytes

// ---------------------------------------------------------------------------
extern "C" void kernel_launch(void* const* d_in, const int* in_sizes, int n_in,
                              void* d_out, int out_size)
{
    const float* q  = (const float*)d_in[0];
    const float* k  = (const float*)d_in[1];
    const float* v  = (const float*)d_in[2];
    const float* qs = (const float*)d_in[3];
    const float* ks = (const float*)d_in[4];
    const float* pw = (const float*)d_in[5];
    const float* pb = (const float*)d_in[6];
    float* out = (float*)d_out;

    cudaFuncSetAttribute(attn_kernel,
        cudaFuncAttributeMaxDynamicSharedMemorySize, ATTN_SMEM);
    cudaFuncSetAttribute(proj_kernel,
        cudaFuncAttributeMaxDynamicSharedMemorySize, PROJ_SMEM);

    prep_kernel<<<BB * NN, 384>>>(q, k, v, qs, ks);
    wsplit_kernel<<<(EE * EE) / 256, 256>>>(pw);
    attn_kernel<<<dim3(NN / BR, BB * HH), 256, ATTN_SMEM>>>();
    proj_kernel<<<dim3(EE / 128, (BB * NN) / 128), 256, PROJ_SMEM>>>(pb, out);
}

// round 15
// speedup vs baseline: 4.3539x; 1.0323x over previous
#include <cuda_runtime.h>
#include <cuda_bf16.h>

#define BB 4
#define NN 2048
#define EE 768
#define HH 12
#define DD 64
#define RD 32

#define BHND ((size_t)BB * HH * NN * DD)      // 6291456
#define YSZ  ((size_t)BB * NN * EE)           // 6291456

// ---- global scratch (allocation-free contract) ----
__device__ float         g_qh [BHND];
__device__ __nv_bfloat16 g_khi[BHND], g_klo[BHND];
__device__ __nv_bfloat16 g_vhi[BHND], g_vlo[BHND];
__device__ __nv_bfloat16 g_yhi[YSZ],  g_ylo[YSZ];
__device__ __nv_bfloat16 g_whi[EE * EE], g_wlo[EE * EE];

// ---- helpers ----
__device__ __forceinline__ unsigned pack2(__nv_bfloat16 a, __nv_bfloat16 b) {
    __nv_bfloat162 t; t.x = a; t.y = b; return *(unsigned*)&t;
}
__device__ __forceinline__ void splitpack(float2 f, unsigned& hi, unsigned& lo) {
    __nv_bfloat16 hx = __float2bfloat16(f.x), hy = __float2bfloat16(f.y);
    __nv_bfloat16 lx = __float2bfloat16(f.x - __bfloat162float(hx));
    __nv_bfloat16 ly = __float2bfloat16(f.y - __bfloat162float(hy));
    hi = pack2(hx, hy); lo = pack2(lx, ly);
}
// Fast 2-wide split: one packed cvt for hi, shift/mask unpack, residual, packed cvt.
__device__ __forceinline__ void splitpack2(float f0, float f1,
                                           unsigned& hi, unsigned& lo) {
    unsigned h;
    asm("cvt.rn.bf16x2.f32 %0, %1, %2;" : "=r"(h) : "f"(f1), "f"(f0));
    const float h0 = __uint_as_float(h << 16);
    const float h1 = __uint_as_float(h & 0xffff0000u);
    const float l0 = f0 - h0;
    const float l1 = f1 - h1;
    unsigned l;
    asm("cvt.rn.bf16x2.f32 %0, %1, %2;" : "=r"(l) : "f"(l1), "f"(l0));
    hi = h; lo = l;
}
__device__ __forceinline__ void mma_bf(float c[4], const unsigned a[4],
                                       unsigned b0, unsigned b1) {
    asm volatile(
        "mma.sync.aligned.m16n8k16.row.col.f32.bf16.bf16.f32 "
        "{%0,%1,%2,%3},{%4,%5,%6,%7},{%8,%9},{%0,%1,%2,%3};\n"
        : "+f"(c[0]), "+f"(c[1]), "+f"(c[2]), "+f"(c[3])
        : "r"(a[0]), "r"(a[1]), "r"(a[2]), "r"(a[3]), "r"(b0), "r"(b1));
}
__device__ __forceinline__ void ldsm4(unsigned& r0, unsigned& r1, unsigned& r2,
                                      unsigned& r3, unsigned addr) {
    asm volatile("ldmatrix.sync.aligned.m8n8.x4.shared.b16 {%0,%1,%2,%3},[%4];\n"
                 : "=r"(r0), "=r"(r1), "=r"(r2), "=r"(r3) : "r"(addr));
}
__device__ __forceinline__ void ldsm4t(unsigned& r0, unsigned& r1, unsigned& r2,
                                       unsigned& r3, unsigned addr) {
    asm volatile("ldmatrix.sync.aligned.m8n8.x4.trans.shared.b16 {%0,%1,%2,%3},[%4];\n"
                 : "=r"(r0), "=r"(r1), "=r"(r2), "=r"(r3) : "r"(addr));
}
__device__ __forceinline__ void cpa16(unsigned dst, const void* src) {
    asm volatile("cp.async.cg.shared.global [%0], [%1], 16;\n"
                 :: "r"(dst), "l"(src));
}
__device__ __forceinline__ void cpcommit() {
    asm volatile("cp.async.commit_group;\n");
}
template <int N> __device__ __forceinline__ void cpwait() {
    asm volatile("cp.async.wait_group %0;\n" :: "n"(N));
}

#define L2E 1.4426950408889634f

// ---------------------------------------------------------------------------
// Kernel 1: RMSNorm + xPos RoPE + head split. Q stays fp32; K/V pre-split to
// bf16 hi/lo planes.
// ---------------------------------------------------------------------------
__global__ __launch_bounds__(384) void prep_kernel(
    const float* __restrict__ q, const float* __restrict__ k,
    const float* __restrict__ v,
    const float* __restrict__ qs, const float* __restrict__ ks)
{
    const int row = blockIdx.x;
    const int b = row / NN;
    const int n = row - b * NN;
    const int w = threadIdx.x >> 5;
    const int l = threadIdx.x & 31;

    const size_t ibase = (size_t)row * EE + w * DD + 2 * l;
    float x0 = q[ibase], x1 = q[ibase + 1];
    float y0 = k[ibase], y1 = k[ibase + 1];
    float v0 = v[ibase], v1 = v[ibase + 1];

    float sq = x0 * x0 + x1 * x1;
    float sk = y0 * y0 + y1 * y1;
    #pragma unroll
    for (int off = 16; off; off >>= 1) {
        sq += __shfl_xor_sync(0xffffffffu, sq, off);
        sk += __shfl_xor_sync(0xffffffffu, sk, off);
    }
    const float rq = rsqrtf(sq * (1.0f / DD) + 1e-6f);
    const float rk = rsqrtf(sk * (1.0f / DD) + 1e-6f);
    x0 *= rq * qs[2 * l]; x1 *= rq * qs[2 * l + 1];
    y0 *= rk * ks[2 * l]; y1 *= rk * ks[2 * l + 1];

    if (l < 16) {
        const float freq = powf(10000.0f, -(float)l / 16.0f);
        float s, c;
        sincosf((float)n * freq, &s, &c);
        const float base  = (2.0f * l + 0.4f * RD) / (1.4f * RD);
        const float power = ((float)n - (float)(NN / 2)) * (1.0f / 512.0f);
        const float sc  = powf(base,  power);
        const float isc = powf(base, -power);
        const float nx0 = (x0 * c - x1 * s) * sc;
        const float nx1 = (x1 * c + x0 * s) * sc;
        const float ny0 = (y0 * c - y1 * s) * isc;
        const float ny1 = (y1 * c + y0 * s) * isc;
        x0 = nx0; x1 = nx1; y0 = ny0; y1 = ny1;
    }

    const size_t ob = (((size_t)b * HH + w) * NN + n) * DD + 2 * l;
    g_qh[ob] = x0; g_qh[ob + 1] = x1;

    unsigned khi, klo, vhi, vlo;
    splitpack(make_float2(y0, y1), khi, klo);
    splitpack(make_float2(v0, v1), vhi, vlo);
    *(unsigned*)(g_khi + ob) = khi; *(unsigned*)(g_klo + ob) = klo;
    *(unsigned*)(g_vhi + ob) = vhi; *(unsigned*)(g_vlo + ob) = vlo;
}

// ---------------------------------------------------------------------------
// Kernel 1b: split W into bf16 hi/lo once.
// ---------------------------------------------------------------------------
__global__ __launch_bounds__(256) void wsplit_kernel(const float* __restrict__ w)
{
    const int i = blockIdx.x * 256 + threadIdx.x;
    const float f = w[i];
    __nv_bfloat16 h = __float2bfloat16(f);
    g_whi[i] = h;
    g_wlo[i] = __float2bfloat16(f - __bfloat162float(h));
}

// ---------------------------------------------------------------------------
// Kernel 2: causal flash attention, split-bf16 mma.sync + cp.async double
// buffering. 2 CTAs/SM (4 warps/SMSP to overlap softmax with HMMA), 1/8
// scale folded exactly into the Q split, fused exp2 softmax, packed-cvt
// splitpack.
// ---------------------------------------------------------------------------
#define BR   128
#define KT   64
#define SROW 72
#define PLANE (64 * SROW)                 // elems per plane
#define STAGE_B (4 * PLANE)               // bytes per K (or V) stage (2 planes)

__global__ __launch_bounds__(256, 2) void attn_kernel()
{
    extern __shared__ __nv_bfloat16 dynsm_a[];
    __nv_bfloat16* smk = dynsm_a;                 // [2 stages][2 planes][PLANE]
    __nv_bfloat16* smv = dynsm_a + 4 * PLANE;

    const int qb   = (int)(gridDim.x - 1 - blockIdx.x);
    const int bh   = blockIdx.y;
    const int tid  = threadIdx.x;
    const int w    = tid >> 5;
    const int lane = tid & 31;
    const int qr0  = qb * BR + w * 16 + (lane >> 2);
    const int qr1  = qr0 + 8;
    const int c2   = (lane & 3) * 2;

    const size_t hb = (size_t)bh * NN * DD;
    const float* __restrict__ Q = g_qh + hb;

    // Q fragments, pre-scaled by 1/sqrt(D)=0.125 (exact: power-of-2 scales
    // both hi and lo split parts exactly), split hi/lo.
    unsigned qhi[4][4], qlo[4][4];
    #pragma unroll
    for (int kc = 0; kc < 4; kc++) {
        const int c0 = kc * 16 + c2;
        float2 a0 = *(const float2*)(Q + (size_t)qr0 * DD + c0);
        float2 a1 = *(const float2*)(Q + (size_t)qr1 * DD + c0);
        float2 a2 = *(const float2*)(Q + (size_t)qr0 * DD + c0 + 8);
        float2 a3 = *(const float2*)(Q + (size_t)qr1 * DD + c0 + 8);
        splitpack2(a0.x * 0.125f, a0.y * 0.125f, qhi[kc][0], qlo[kc][0]);
        splitpack2(a1.x * 0.125f, a1.y * 0.125f, qhi[kc][1], qlo[kc][1]);
        splitpack2(a2.x * 0.125f, a2.y * 0.125f, qhi[kc][2], qlo[kc][2]);
        splitpack2(a3.x * 0.125f, a3.y * 0.125f, qhi[kc][3], qlo[kc][3]);
    }

    float oacc[8][4];
    #pragma unroll
    for (int i = 0; i < 8; i++)
        #pragma unroll
        for (int jj = 0; jj < 4; jj++) oacc[i][jj] = 0.f;
    float mA = -1e30f, mB = -1e30f, lA = 0.f, lB = 0.f;

    const unsigned skb = (unsigned)__cvta_generic_to_shared(smk);
    const unsigned svb = (unsigned)__cvta_generic_to_shared(smv);
    const int pl = lane >> 4;
    const unsigned kbase0 = skb + (unsigned)(pl * PLANE + (lane & 7) * SROW +
                                             ((lane & 8) ? 8 : 0)) * 2;
    const unsigned vbase0 = svb + (unsigned)(pl * PLANE + (lane & 15) * SROW) * 2;

    const int l_row = tid >> 3;
    const int l_cc  = (tid & 7) * 8;
    const unsigned l_off0 = (unsigned)(l_row * SROW + l_cc) * 2;
    const unsigned l_off1 = (unsigned)((l_row + 32) * SROW + l_cc) * 2;
    const size_t g_off0 = (size_t)l_row * DD + l_cc;
    const size_t g_off1 = (size_t)(l_row + 32) * DD + l_cc;

    const int wrow_max = qb * BR + w * 16 + 15;
    const int jmax = 2 * qb + 1;

    {
        const size_t tb = hb;
        const unsigned sk0 = skb, sv0 = svb;
        cpa16(sk0 + l_off0,             g_khi + tb + g_off0);
        cpa16(sk0 + l_off1,             g_khi + tb + g_off1);
        cpa16(sk0 + PLANE * 2 + l_off0, g_klo + tb + g_off0);
        cpa16(sk0 + PLANE * 2 + l_off1, g_klo + tb + g_off1);
        cpa16(sv0 + l_off0,             g_vhi + tb + g_off0);
        cpa16(sv0 + l_off1,             g_vhi + tb + g_off1);
        cpa16(sv0 + PLANE * 2 + l_off0, g_vlo + tb + g_off0);
        cpa16(sv0 + PLANE * 2 + l_off1, g_vlo + tb + g_off1);
        cpcommit();
    }

    for (int j = 0; j <= jmax; j++) {
        const int kb  = j * KT;
        const int cur = j & 1;

        if (j < jmax) {
            const size_t tb = hb + (size_t)(kb + KT) * DD;
            const unsigned sb = (unsigned)((cur ^ 1) * STAGE_B);
            const unsigned sk1 = skb + sb, sv1 = svb + sb;
            cpa16(sk1 + l_off0,             g_khi + tb + g_off0);
            cpa16(sk1 + l_off1,             g_khi + tb + g_off1);
            cpa16(sk1 + PLANE * 2 + l_off0, g_klo + tb + g_off0);
            cpa16(sk1 + PLANE * 2 + l_off1, g_klo + tb + g_off1);
            cpa16(sv1 + l_off0,             g_vhi + tb + g_off0);
            cpa16(sv1 + l_off1,             g_vhi + tb + g_off1);
            cpa16(sv1 + PLANE * 2 + l_off0, g_vlo + tb + g_off0);
            cpa16(sv1 + PLANE * 2 + l_off1, g_vlo + tb + g_off1);
            cpcommit();
            cpwait<1>();
        } else {
            cpwait<0>();
        }
        __syncthreads();

        if (kb <= wrow_max) {
            const unsigned kbase = kbase0 + (unsigned)(cur * STAGE_B);
            const unsigned vbase = vbase0 + (unsigned)(cur * STAGE_B);

            // ---- S = (Q/8) K^T (already scaled) ----
            float sacc[8][4];
            #pragma unroll
            for (int nt = 0; nt < 8; nt++)
                #pragma unroll
                for (int i = 0; i < 4; i++) sacc[nt][i] = 0.f;

            #pragma unroll
            for (int kc = 0; kc < 4; kc++) {
                #pragma unroll
                for (int nt = 0; nt < 8; nt++) {
                    unsigned r0, r1, r2, r3;
                    ldsm4(r0, r1, r2, r3,
                          kbase + (unsigned)(nt * 8 * SROW * 2 + kc * 32));
                    mma_bf(sacc[nt], qhi[kc], r0, r1);
                    mma_bf(sacc[nt], qhi[kc], r2, r3);
                    mma_bf(sacc[nt], qlo[kc], r0, r1);
                }
            }

            // ---- online softmax (fused exp2) ----
            const bool mk0 = (kb + 63 > qr0);
            float mtA = -1e30f, mtB = -1e30f;
            #pragma unroll
            for (int nt = 0; nt < 8; nt++) {
                float s0 = sacc[nt][0], s1 = sacc[nt][1];
                float s2 = sacc[nt][2], s3 = sacc[nt][3];
                if (mk0) {
                    const int col = kb + nt * 8 + c2;
                    if (col     > qr0) s0 = -1e30f;
                    if (col + 1 > qr0) s1 = -1e30f;
                    if (col     > qr1) s2 = -1e30f;
                    if (col + 1 > qr1) s3 = -1e30f;
                    sacc[nt][0] = s0; sacc[nt][1] = s1;
                    sacc[nt][2] = s2; sacc[nt][3] = s3;
                }
                mtA = fmaxf(mtA, fmaxf(s0, s1));
                mtB = fmaxf(mtB, fmaxf(s2, s3));
            }
            mtA = fmaxf(mtA, __shfl_xor_sync(0xffffffffu, mtA, 1));
            mtA = fmaxf(mtA, __shfl_xor_sync(0xffffffffu, mtA, 2));
            mtB = fmaxf(mtB, __shfl_xor_sync(0xffffffffu, mtB, 1));
            mtB = fmaxf(mtB, __shfl_xor_sync(0xffffffffu, mtB, 2));
            const float mnA = fmaxf(mA, mtA), mnB = fmaxf(mB, mtB);
            const float aA = exp2f((mA - mnA) * L2E);
            const float aB = exp2f((mB - mnB) * L2E);
            mA = mnA; mB = mnB;
            const float mnlA = mnA * L2E, mnlB = mnB * L2E;
            lA *= aA; lB *= aB;
            #pragma unroll
            for (int dt = 0; dt < 8; dt++) {
                oacc[dt][0] *= aA; oacc[dt][1] *= aA;
                oacc[dt][2] *= aB; oacc[dt][3] *= aB;
            }
            #pragma unroll
            for (int nt = 0; nt < 8; nt++) {
                const float p0 = exp2f(fmaf(sacc[nt][0], L2E, -mnlA));
                const float p1 = exp2f(fmaf(sacc[nt][1], L2E, -mnlA));
                const float p2 = exp2f(fmaf(sacc[nt][2], L2E, -mnlB));
                const float p3 = exp2f(fmaf(sacc[nt][3], L2E, -mnlB));
                lA += p0 + p1; lB += p2 + p3;
                sacc[nt][0] = p0; sacc[nt][1] = p1;
                sacc[nt][2] = p2; sacc[nt][3] = p3;
            }

            // ---- O += P V ----
            #pragma unroll
            for (int kc = 0; kc < 4; kc++) {
                unsigned phi[4], plo2[4];
                splitpack2(sacc[2*kc][0],   sacc[2*kc][1],   phi[0], plo2[0]);
                splitpack2(sacc[2*kc][2],   sacc[2*kc][3],   phi[1], plo2[1]);
                splitpack2(sacc[2*kc+1][0], sacc[2*kc+1][1], phi[2], plo2[2]);
                splitpack2(sacc[2*kc+1][2], sacc[2*kc+1][3], phi[3], plo2[3]);
                #pragma unroll
                for (int dt = 0; dt < 8; dt++) {
                    unsigned r0, r1, r2, r3;
                    ldsm4t(r0, r1, r2, r3,
                           vbase + (unsigned)(kc * 16 * SROW * 2 + dt * 16));
                    mma_bf(oacc[dt], phi,  r0, r1);
                    mma_bf(oacc[dt], phi,  r2, r3);
                    mma_bf(oacc[dt], plo2, r0, r1);
                }
            }
        }
        __syncthreads();
    }

    lA += __shfl_xor_sync(0xffffffffu, lA, 1);
    lA += __shfl_xor_sync(0xffffffffu, lA, 2);
    lB += __shfl_xor_sync(0xffffffffu, lB, 1);
    lB += __shfl_xor_sync(0xffffffffu, lB, 2);
    const float iA = __fdividef(1.0f, lA);
    const float iB = __fdividef(1.0f, lB);

    const int b = bh / HH, h = bh - b * HH;
    const size_t r0b = ((size_t)b * NN + qr0) * EE + h * DD;
    const size_t r1b = ((size_t)b * NN + qr1) * EE + h * DD;
    #pragma unroll
    for (int dt = 0; dt < 8; dt++) {
        const int col = dt * 8 + c2;
        unsigned hi, lo;
        splitpack2(oacc[dt][0] * iA, oacc[dt][1] * iA, hi, lo);
        *(unsigned*)(g_yhi + r0b + col) = hi;
        *(unsigned*)(g_ylo + r0b + col) = lo;
        splitpack2(oacc[dt][2] * iB, oacc[dt][3] * iB, hi, lo);
        *(unsigned*)(g_yhi + r1b + col) = hi;
        *(unsigned*)(g_ylo + r1b + col) = lo;
    }
}

// ---------------------------------------------------------------------------
// Kernel 3: out = Y W^T + b, split-bf16 mma.sync, cp.async double-buffered
// k-stages (the measured round-7 version; tcgen05 is not expressible in this
// harness's PTX target).
// ---------------------------------------------------------------------------
#define PROW   40
#define APLANE (128 * PROW)               // elems per plane
#define PSTG_B (4 * APLANE)               // bytes per stage (2 planes)
#define NKIT   (EE / 32)                  // 24 k-stages

__global__ __launch_bounds__(256, 2) void proj_kernel(
    const float* __restrict__ bias, float* __restrict__ out)
{
    extern __shared__ __nv_bfloat16 dynsm_p[];
    __nv_bfloat16* sA = dynsm_p;                  // [2 stages][hi,lo][APLANE]
    __nv_bfloat16* sB = dynsm_p + 4 * APLANE;

    const int tid = threadIdx.x, w = tid >> 5, lane = tid & 31;
    const int bm = blockIdx.y * 128, bn = blockIdx.x * 128;
    const int wm = w >> 2, wn = w & 3;

    float acc[4][4][4];
    #pragma unroll
    for (int a = 0; a < 4; a++)
        #pragma unroll
        for (int b2 = 0; b2 < 4; b2++)
            #pragma unroll
            for (int c = 0; c < 4; c++) acc[a][b2][c] = 0.f;

    const unsigned sab = (unsigned)__cvta_generic_to_shared(sA);
    const unsigned sbb = (unsigned)__cvta_generic_to_shared(sB);
    const unsigned abase0 = sab + (unsigned)((wm * 64 + (lane & 15)) * PROW +
                                             ((lane & 16) ? 8 : 0)) * 2;
    const unsigned bbase0 = sbb + (unsigned)((lane >> 4) * APLANE +
                                             (wn * 32 + (lane & 7)) * PROW +
                                             ((lane & 8) ? 8 : 0)) * 2;

    auto load_stage = [&](int stage, int k0) {
        const unsigned sb = (unsigned)(stage * PSTG_B);
        #pragma unroll
        for (int p = 0; p < 8; p++) {
            const int i = tid + p * 256;
            const int plane = i >> 9;
            const int rem = i & 511;
            const int row = rem >> 2;
            const int cc  = (rem & 3) * 8;
            const unsigned doff = sb + (unsigned)((plane & 1) * APLANE +
                                                  row * PROW + cc) * 2;
            if (plane == 0)
                cpa16(sab + doff, g_yhi + (size_t)(bm + row) * EE + k0 + cc);
            else if (plane == 1)
                cpa16(sab + doff, g_ylo + (size_t)(bm + row) * EE + k0 + cc);
            else if (plane == 2)
                cpa16(sbb + doff, g_whi + (size_t)(bn + row) * EE + k0 + cc);
            else
                cpa16(sbb + doff, g_wlo + (size_t)(bn + row) * EE + k0 + cc);
        }
        cpcommit();
    };

    load_stage(0, 0);

    for (int it = 0; it < NKIT; it++) {
        const int cur = it & 1;
        if (it < NKIT - 1) { load_stage(cur ^ 1, (it + 1) * 32); cpwait<1>(); }
        else               { cpwait<0>(); }
        __syncthreads();

        const unsigned abase = abase0 + (unsigned)(cur * PSTG_B);
        const unsigned bbase = bbase0 + (unsigned)(cur * PSTG_B);

        #pragma unroll
        for (int kc = 0; kc < 2; kc++) {
            unsigned ahi[4][4], alo[4][4];
            #pragma unroll
            for (int mi = 0; mi < 4; mi++) {
                ldsm4(ahi[mi][0], ahi[mi][1], ahi[mi][2], ahi[mi][3],
                      abase + (unsigned)(mi * 16 * PROW * 2 + kc * 32));
                ldsm4(alo[mi][0], alo[mi][1], alo[mi][2], alo[mi][3],
                      abase + (unsigned)(APLANE * 2 + mi * 16 * PROW * 2 + kc * 32));
            }
            #pragma unroll
            for (int ni = 0; ni < 4; ni++) {
                unsigned r0, r1, r2, r3;
                ldsm4(r0, r1, r2, r3,
                      bbase + (unsigned)(ni * 8 * PROW * 2 + kc * 32));
                #pragma unroll
                for (int mi = 0; mi < 4; mi++) {
                    mma_bf(acc[mi][ni], ahi[mi], r0, r1);
                    mma_bf(acc[mi][ni], ahi[mi], r2, r3);
                    mma_bf(acc[mi][ni], alo[mi], r0, r1);
                }
            }
        }
        __syncthreads();
    }

    const int rA = bm + wm * 64 + (lane >> 2);
    #pragma unroll
    for (int mi = 0; mi < 4; mi++) {
        const int r0 = rA + mi * 16, r1 = r0 + 8;
        #pragma unroll
        for (int ni = 0; ni < 4; ni++) {
            const int col = bn + wn * 32 + ni * 8 + (lane & 3) * 2;
            const float b0 = bias[col], b1 = bias[col + 1];
            *(float2*)(out + (size_t)r0 * EE + col) =
                make_float2(acc[mi][ni][0] + b0, acc[mi][ni][1] + b1);
            *(float2*)(out + (size_t)r1 * EE + col) =
                make_float2(acc[mi][ni][2] + b0, acc[mi][ni][3] + b1);
        }
    }
}

#define ATTN_SMEM (8 * PLANE * 2)         // 73728 bytes
#define PROJ_SMEM (8 * APLANE * 2)        // 81920 bytes

// ---------------------------------------------------------------------------
extern "C" void kernel_launch(void* const* d_in, const int* in_sizes, int n_in,
                              void* d_out, int out_size)
{
    const float* q  = (const float*)d_in[0];
    const float* k  = (const float*)d_in[1];
    const float* v  = (const float*)d_in[2];
    const float* qs = (const float*)d_in[3];
    const float* ks = (const float*)d_in[4];
    const float* pw = (const float*)d_in[5];
    const float* pb = (const float*)d_in[6];
    float* out = (float*)d_out;

    cudaFuncSetAttribute(attn_kernel,
        cudaFuncAttributeMaxDynamicSharedMemorySize, ATTN_SMEM);
    cudaFuncSetAttribute(proj_kernel,
        cudaFuncAttributeMaxDynamicSharedMemorySize, PROJ_SMEM);

    prep_kernel<<<BB * NN, 384>>>(q, k, v, qs, ks);
    wsplit_kernel<<<(EE * EE) / 256, 256>>>(pw);
    attn_kernel<<<dim3(NN / BR, BB * HH), 256, ATTN_SMEM>>>();
    proj_kernel<<<dim3(EE / 128, (BB * NN) / 128), 256, PROJ_SMEM>>>(pb, out);
}

// round 17
// speedup vs baseline: 4.6492x; 1.0678x over previous
#include <cuda_runtime.h>
#include <cuda_bf16.h>

#define BB 4
#define NN 2048
#define EE 768
#define HH 12
#define DD 64
#define RD 32

#define BHND ((size_t)BB * HH * NN * DD)      // 6291456
#define YSZ  ((size_t)BB * NN * EE)           // 6291456

// ---- global scratch (allocation-free contract) ----
__device__ float         g_qh [BHND];
__device__ __nv_bfloat16 g_khi[BHND], g_klo[BHND];
__device__ __nv_bfloat16 g_vhi[BHND], g_vlo[BHND];
__device__ float         g_y  [YSZ];

// ---- helpers ----
__device__ __forceinline__ unsigned pack2(__nv_bfloat16 a, __nv_bfloat16 b) {
    __nv_bfloat162 t; t.x = a; t.y = b; return *(unsigned*)&t;
}
__device__ __forceinline__ void splitpack(float2 f, unsigned& hi, unsigned& lo) {
    __nv_bfloat16 hx = __float2bfloat16(f.x), hy = __float2bfloat16(f.y);
    __nv_bfloat16 lx = __float2bfloat16(f.x - __bfloat162float(hx));
    __nv_bfloat16 ly = __float2bfloat16(f.y - __bfloat162float(hy));
    hi = pack2(hx, hy); lo = pack2(lx, ly);
}
// Fast 2-wide split: one packed cvt for hi, shift/mask unpack, residual, packed cvt.
__device__ __forceinline__ void splitpack2(float f0, float f1,
                                           unsigned& hi, unsigned& lo) {
    unsigned h;
    asm("cvt.rn.bf16x2.f32 %0, %1, %2;" : "=r"(h) : "f"(f1), "f"(f0));
    const float h0 = __uint_as_float(h << 16);
    const float h1 = __uint_as_float(h & 0xffff0000u);
    const float l0 = f0 - h0;
    const float l1 = f1 - h1;
    unsigned l;
    asm("cvt.rn.bf16x2.f32 %0, %1, %2;" : "=r"(l) : "f"(l1), "f"(l0));
    hi = h; lo = l;
}
__device__ __forceinline__ void mma_bf(float c[4], const unsigned a[4],
                                       unsigned b0, unsigned b1) {
    asm volatile(
        "mma.sync.aligned.m16n8k16.row.col.f32.bf16.bf16.f32 "
        "{%0,%1,%2,%3},{%4,%5,%6,%7},{%8,%9},{%0,%1,%2,%3};\n"
        : "+f"(c[0]), "+f"(c[1]), "+f"(c[2]), "+f"(c[3])
        : "r"(a[0]), "r"(a[1]), "r"(a[2]), "r"(a[3]), "r"(b0), "r"(b1));
}
__device__ __forceinline__ void mma_tf(float c[4], unsigned a0, unsigned a1,
                                       unsigned a2, unsigned a3,
                                       unsigned b0, unsigned b1) {
    asm volatile(
        "mma.sync.aligned.m16n8k8.row.col.f32.tf32.tf32.f32 "
        "{%0,%1,%2,%3},{%4,%5,%6,%7},{%8,%9},{%0,%1,%2,%3};\n"
        : "+f"(c[0]), "+f"(c[1]), "+f"(c[2]), "+f"(c[3])
        : "r"(a0), "r"(a1), "r"(a2), "r"(a3), "r"(b0), "r"(b1));
}
__device__ __forceinline__ unsigned f2tf(float x) {
    unsigned r;
    asm("cvt.rna.tf32.f32 %0, %1;" : "=r"(r) : "f"(x));
    return r;
}
__device__ __forceinline__ void ldsm4(unsigned& r0, unsigned& r1, unsigned& r2,
                                      unsigned& r3, unsigned addr) {
    asm volatile("ldmatrix.sync.aligned.m8n8.x4.shared.b16 {%0,%1,%2,%3},[%4];\n"
                 : "=r"(r0), "=r"(r1), "=r"(r2), "=r"(r3) : "r"(addr));
}
__device__ __forceinline__ void ldsm4t(unsigned& r0, unsigned& r1, unsigned& r2,
                                       unsigned& r3, unsigned addr) {
    asm volatile("ldmatrix.sync.aligned.m8n8.x4.trans.shared.b16 {%0,%1,%2,%3},[%4];\n"
                 : "=r"(r0), "=r"(r1), "=r"(r2), "=r"(r3) : "r"(addr));
}
__device__ __forceinline__ void cpa16(unsigned dst, const void* src) {
    asm volatile("cp.async.cg.shared.global [%0], [%1], 16;\n"
                 :: "r"(dst), "l"(src));
}
__device__ __forceinline__ void cpcommit() {
    asm volatile("cp.async.commit_group;\n");
}
template <int N> __device__ __forceinline__ void cpwait() {
    asm volatile("cp.async.wait_group %0;\n" :: "n"(N));
}

#define L2E 1.4426950408889634f

// ---------------------------------------------------------------------------
// Kernel 1: RMSNorm + xPos RoPE + head split. Q stays fp32; K/V pre-split to
// bf16 hi/lo planes.
// ---------------------------------------------------------------------------
__global__ __launch_bounds__(384) void prep_kernel(
    const float* __restrict__ q, const float* __restrict__ k,
    const float* __restrict__ v,
    const float* __restrict__ qs, const float* __restrict__ ks)
{
    const int row = blockIdx.x;
    const int b = row / NN;
    const int n = row - b * NN;
    const int w = threadIdx.x >> 5;
    const int l = threadIdx.x & 31;

    const size_t ibase = (size_t)row * EE + w * DD + 2 * l;
    float x0 = q[ibase], x1 = q[ibase + 1];
    float y0 = k[ibase], y1 = k[ibase + 1];
    float v0 = v[ibase], v1 = v[ibase + 1];

    float sq = x0 * x0 + x1 * x1;
    float sk = y0 * y0 + y1 * y1;
    #pragma unroll
    for (int off = 16; off; off >>= 1) {
        sq += __shfl_xor_sync(0xffffffffu, sq, off);
        sk += __shfl_xor_sync(0xffffffffu, sk, off);
    }
    const float rq = rsqrtf(sq * (1.0f / DD) + 1e-6f);
    const float rk = rsqrtf(sk * (1.0f / DD) + 1e-6f);
    x0 *= rq * qs[2 * l]; x1 *= rq * qs[2 * l + 1];
    y0 *= rk * ks[2 * l]; y1 *= rk * ks[2 * l + 1];

    if (l < 16) {
        const float freq = powf(10000.0f, -(float)l / 16.0f);
        float s, c;
        sincosf((float)n * freq, &s, &c);
        const float base  = (2.0f * l + 0.4f * RD) / (1.4f * RD);
        const float power = ((float)n - (float)(NN / 2)) * (1.0f / 512.0f);
        const float sc  = powf(base,  power);
        const float isc = powf(base, -power);
        const float nx0 = (x0 * c - x1 * s) * sc;
        const float nx1 = (x1 * c + x0 * s) * sc;
        const float ny0 = (y0 * c - y1 * s) * isc;
        const float ny1 = (y1 * c + y0 * s) * isc;
        x0 = nx0; x1 = nx1; y0 = ny0; y1 = ny1;
    }

    const size_t ob = (((size_t)b * HH + w) * NN + n) * DD + 2 * l;
    g_qh[ob] = x0; g_qh[ob + 1] = x1;

    unsigned khi, klo, vhi, vlo;
    splitpack(make_float2(y0, y1), khi, klo);
    splitpack(make_float2(v0, v1), vhi, vlo);
    *(unsigned*)(g_khi + ob) = khi; *(unsigned*)(g_klo + ob) = klo;
    *(unsigned*)(g_vhi + ob) = vhi; *(unsigned*)(g_vlo + ob) = vlo;
}

// ---------------------------------------------------------------------------
// Kernel 2: causal flash attention, split-bf16 mma.sync + cp.async double
// buffering, 2 CTAs/SM, folded 1/8 scale, fused exp2 softmax. Epilogue
// writes y as plain fp32 (proj consumes fp32 directly via tf32).
// ---------------------------------------------------------------------------
#define BR   128
#define KT   64
#define SROW 72
#define PLANE (64 * SROW)                 // elems per plane
#define STAGE_B (4 * PLANE)               // bytes per K (or V) stage (2 planes)

__global__ __launch_bounds__(256, 2) void attn_kernel()
{
    extern __shared__ __nv_bfloat16 dynsm_a[];
    __nv_bfloat16* smk = dynsm_a;                 // [2 stages][2 planes][PLANE]
    __nv_bfloat16* smv = dynsm_a + 4 * PLANE;

    const int qb   = (int)(gridDim.x - 1 - blockIdx.x);
    const int bh   = blockIdx.y;
    const int tid  = threadIdx.x;
    const int w    = tid >> 5;
    const int lane = tid & 31;
    const int qr0  = qb * BR + w * 16 + (lane >> 2);
    const int qr1  = qr0 + 8;
    const int c2   = (lane & 3) * 2;

    const size_t hb = (size_t)bh * NN * DD;
    const float* __restrict__ Q = g_qh + hb;

    unsigned qhi[4][4], qlo[4][4];
    #pragma unroll
    for (int kc = 0; kc < 4; kc++) {
        const int c0 = kc * 16 + c2;
        float2 a0 = *(const float2*)(Q + (size_t)qr0 * DD + c0);
        float2 a1 = *(const float2*)(Q + (size_t)qr1 * DD + c0);
        float2 a2 = *(const float2*)(Q + (size_t)qr0 * DD + c0 + 8);
        float2 a3 = *(const float2*)(Q + (size_t)qr1 * DD + c0 + 8);
        splitpack2(a0.x * 0.125f, a0.y * 0.125f, qhi[kc][0], qlo[kc][0]);
        splitpack2(a1.x * 0.125f, a1.y * 0.125f, qhi[kc][1], qlo[kc][1]);
        splitpack2(a2.x * 0.125f, a2.y * 0.125f, qhi[kc][2], qlo[kc][2]);
        splitpack2(a3.x * 0.125f, a3.y * 0.125f, qhi[kc][3], qlo[kc][3]);
    }

    float oacc[8][4];
    #pragma unroll
    for (int i = 0; i < 8; i++)
        #pragma unroll
        for (int jj = 0; jj < 4; jj++) oacc[i][jj] = 0.f;
    float mA = -1e30f, mB = -1e30f, lA = 0.f, lB = 0.f;

    const unsigned skb = (unsigned)__cvta_generic_to_shared(smk);
    const unsigned svb = (unsigned)__cvta_generic_to_shared(smv);
    const int pl = lane >> 4;
    const unsigned kbase0 = skb + (unsigned)(pl * PLANE + (lane & 7) * SROW +
                                             ((lane & 8) ? 8 : 0)) * 2;
    const unsigned vbase0 = svb + (unsigned)(pl * PLANE + (lane & 15) * SROW) * 2;

    const int l_row = tid >> 3;
    const int l_cc  = (tid & 7) * 8;
    const unsigned l_off0 = (unsigned)(l_row * SROW + l_cc) * 2;
    const unsigned l_off1 = (unsigned)((l_row + 32) * SROW + l_cc) * 2;
    const size_t g_off0 = (size_t)l_row * DD + l_cc;
    const size_t g_off1 = (size_t)(l_row + 32) * DD + l_cc;

    const int wrow_max = qb * BR + w * 16 + 15;
    const int jmax = 2 * qb + 1;

    {
        const size_t tb = hb;
        const unsigned sk0 = skb, sv0 = svb;
        cpa16(sk0 + l_off0,             g_khi + tb + g_off0);
        cpa16(sk0 + l_off1,             g_khi + tb + g_off1);
        cpa16(sk0 + PLANE * 2 + l_off0, g_klo + tb + g_off0);
        cpa16(sk0 + PLANE * 2 + l_off1, g_klo + tb + g_off1);
        cpa16(sv0 + l_off0,             g_vhi + tb + g_off0);
        cpa16(sv0 + l_off1,             g_vhi + tb + g_off1);
        cpa16(sv0 + PLANE * 2 + l_off0, g_vlo + tb + g_off0);
        cpa16(sv0 + PLANE * 2 + l_off1, g_vlo + tb + g_off1);
        cpcommit();
    }

    for (int j = 0; j <= jmax; j++) {
        const int kb  = j * KT;
        const int cur = j & 1;

        if (j < jmax) {
            const size_t tb = hb + (size_t)(kb + KT) * DD;
            const unsigned sb = (unsigned)((cur ^ 1) * STAGE_B);
            const unsigned sk1 = skb + sb, sv1 = svb + sb;
            cpa16(sk1 + l_off0,             g_khi + tb + g_off0);
            cpa16(sk1 + l_off1,             g_khi + tb + g_off1);
            cpa16(sk1 + PLANE * 2 + l_off0, g_klo + tb + g_off0);
            cpa16(sk1 + PLANE * 2 + l_off1, g_klo + tb + g_off1);
            cpa16(sv1 + l_off0,             g_vhi + tb + g_off0);
            cpa16(sv1 + l_off1,             g_vhi + tb + g_off1);
            cpa16(sv1 + PLANE * 2 + l_off0, g_vlo + tb + g_off0);
            cpa16(sv1 + PLANE * 2 + l_off1, g_vlo + tb + g_off1);
            cpcommit();
            cpwait<1>();
        } else {
            cpwait<0>();
        }
        __syncthreads();

        if (kb <= wrow_max) {
            const unsigned kbase = kbase0 + (unsigned)(cur * STAGE_B);
            const unsigned vbase = vbase0 + (unsigned)(cur * STAGE_B);

            float sacc[8][4];
            #pragma unroll
            for (int nt = 0; nt < 8; nt++)
                #pragma unroll
                for (int i = 0; i < 4; i++) sacc[nt][i] = 0.f;

            #pragma unroll
            for (int kc = 0; kc < 4; kc++) {
                #pragma unroll
                for (int nt = 0; nt < 8; nt++) {
                    unsigned r0, r1, r2, r3;
                    ldsm4(r0, r1, r2, r3,
                          kbase + (unsigned)(nt * 8 * SROW * 2 + kc * 32));
                    mma_bf(sacc[nt], qhi[kc], r0, r1);
                    mma_bf(sacc[nt], qhi[kc], r2, r3);
                    mma_bf(sacc[nt], qlo[kc], r0, r1);
                }
            }

            const bool mk0 = (kb + 63 > qr0);
            float mtA = -1e30f, mtB = -1e30f;
            #pragma unroll
            for (int nt = 0; nt < 8; nt++) {
                float s0 = sacc[nt][0], s1 = sacc[nt][1];
                float s2 = sacc[nt][2], s3 = sacc[nt][3];
                if (mk0) {
                    const int col = kb + nt * 8 + c2;
                    if (col     > qr0) s0 = -1e30f;
                    if (col + 1 > qr0) s1 = -1e30f;
                    if (col     > qr1) s2 = -1e30f;
                    if (col + 1 > qr1) s3 = -1e30f;
                    sacc[nt][0] = s0; sacc[nt][1] = s1;
                    sacc[nt][2] = s2; sacc[nt][3] = s3;
                }
                mtA = fmaxf(mtA, fmaxf(s0, s1));
                mtB = fmaxf(mtB, fmaxf(s2, s3));
            }
            mtA = fmaxf(mtA, __shfl_xor_sync(0xffffffffu, mtA, 1));
            mtA = fmaxf(mtA, __shfl_xor_sync(0xffffffffu, mtA, 2));
            mtB = fmaxf(mtB, __shfl_xor_sync(0xffffffffu, mtB, 1));
            mtB = fmaxf(mtB, __shfl_xor_sync(0xffffffffu, mtB, 2));
            const float mnA = fmaxf(mA, mtA), mnB = fmaxf(mB, mtB);
            const float aA = exp2f((mA - mnA) * L2E);
            const float aB = exp2f((mB - mnB) * L2E);
            mA = mnA; mB = mnB;
            const float mnlA = mnA * L2E, mnlB = mnB * L2E;
            lA *= aA; lB *= aB;
            #pragma unroll
            for (int dt = 0; dt < 8; dt++) {
                oacc[dt][0] *= aA; oacc[dt][1] *= aA;
                oacc[dt][2] *= aB; oacc[dt][3] *= aB;
            }
            #pragma unroll
            for (int nt = 0; nt < 8; nt++) {
                const float p0 = exp2f(fmaf(sacc[nt][0], L2E, -mnlA));
                const float p1 = exp2f(fmaf(sacc[nt][1], L2E, -mnlA));
                const float p2 = exp2f(fmaf(sacc[nt][2], L2E, -mnlB));
                const float p3 = exp2f(fmaf(sacc[nt][3], L2E, -mnlB));
                lA += p0 + p1; lB += p2 + p3;
                sacc[nt][0] = p0; sacc[nt][1] = p1;
                sacc[nt][2] = p2; sacc[nt][3] = p3;
            }

            #pragma unroll
            for (int kc = 0; kc < 4; kc++) {
                unsigned phi[4], plo2[4];
                splitpack2(sacc[2*kc][0],   sacc[2*kc][1],   phi[0], plo2[0]);
                splitpack2(sacc[2*kc][2],   sacc[2*kc][3],   phi[1], plo2[1]);
                splitpack2(sacc[2*kc+1][0], sacc[2*kc+1][1], phi[2], plo2[2]);
                splitpack2(sacc[2*kc+1][2], sacc[2*kc+1][3], phi[3], plo2[3]);
                #pragma unroll
                for (int dt = 0; dt < 8; dt++) {
                    unsigned r0, r1, r2, r3;
                    ldsm4t(r0, r1, r2, r3,
                           vbase + (unsigned)(kc * 16 * SROW * 2 + dt * 16));
                    mma_bf(oacc[dt], phi,  r0, r1);
                    mma_bf(oacc[dt], phi,  r2, r3);
                    mma_bf(oacc[dt], plo2, r0, r1);
                }
            }
        }
        __syncthreads();
    }

    lA += __shfl_xor_sync(0xffffffffu, lA, 1);
    lA += __shfl_xor_sync(0xffffffffu, lA, 2);
    lB += __shfl_xor_sync(0xffffffffu, lB, 1);
    lB += __shfl_xor_sync(0xffffffffu, lB, 2);
    const float iA = __fdividef(1.0f, lA);
    const float iB = __fdividef(1.0f, lB);

    const int b = bh / HH, h = bh - b * HH;
    const size_t r0b = ((size_t)b * NN + qr0) * EE + h * DD;
    const size_t r1b = ((size_t)b * NN + qr1) * EE + h * DD;
    #pragma unroll
    for (int dt = 0; dt < 8; dt++) {
        const int col = dt * 8 + c2;
        *(float2*)(g_y + r0b + col) =
            make_float2(oacc[dt][0] * iA, oacc[dt][1] * iA);
        *(float2*)(g_y + r1b + col) =
            make_float2(oacc[dt][2] * iB, oacc[dt][3] * iB);
    }
}

// ---------------------------------------------------------------------------
// Kernel 3: out = Y W^T + b via single-pass tf32 mma (m16n8k8), fp32
// operands, cp.async double-buffered 32-wide k-stages. 2 mma/k16 instead of
// the 3 of split-bf16 -> 2/3 the HMMA instruction count.
// ---------------------------------------------------------------------------
#define PROWF  36                         // padded fp32 row stride (144 B)
#define FPLANE (128 * PROWF)              // floats per matrix per stage
#define NKIT   (EE / 32)                  // 24 k-stages

__global__ __launch_bounds__(256, 2) void proj_kernel(
    const float* __restrict__ wmat, const float* __restrict__ bias,
    float* __restrict__ out)
{
    extern __shared__ float dynsm_f[];
    float* sA = dynsm_f;                  // [2 stages][FPLANE]
    float* sB = dynsm_f + 2 * FPLANE;

    const int tid = threadIdx.x, w = tid >> 5, lane = tid & 31;
    const int bm = blockIdx.y * 128, bn = blockIdx.x * 128;
    const int wm = w >> 2, wn = w & 3;
    const int lr = lane >> 2;             // 0..7
    const int lc = lane & 3;              // 0..3

    float acc[4][4][4];
    #pragma unroll
    for (int a = 0; a < 4; a++)
        #pragma unroll
        for (int b2 = 0; b2 < 4; b2++)
            #pragma unroll
            for (int c = 0; c < 4; c++) acc[a][b2][c] = 0.f;

    const unsigned sab = (unsigned)__cvta_generic_to_shared(sA);
    const unsigned sbb = (unsigned)__cvta_generic_to_shared(sB);

    // loader: per stage, per matrix 1024 float4 -> 4 iters x 256 threads
    auto load_stage = [&](int stage, int k0) {
        const unsigned so = (unsigned)(stage * FPLANE * 4);
        #pragma unroll
        for (int p = 0; p < 4; p++) {
            const int i   = tid + p * 256;        // 0..1023
            const int row = i >> 3;
            const int c4  = (i & 7) * 4;          // float col
            const unsigned doff = so + (unsigned)(row * PROWF + c4) * 4;
            cpa16(sab + doff, g_y  + (size_t)(bm + row) * EE + k0 + c4);
            cpa16(sbb + doff, wmat + (size_t)(bn + row) * EE + k0 + c4);
        }
        cpcommit();
    };

    load_stage(0, 0);

    for (int it = 0; it < NKIT; it++) {
        const int cur = it & 1;
        if (it < NKIT - 1) { load_stage(cur ^ 1, (it + 1) * 32); cpwait<1>(); }
        else               { cpwait<0>(); }
        __syncthreads();

        const float* cA = sA + cur * FPLANE;
        const float* cB = sB + cur * FPLANE;

        #pragma unroll
        for (int kc = 0; kc < 4; kc++) {          // 4 x k8
            const int kk = kc * 8 + lc;
            unsigned af[4][4];
            #pragma unroll
            for (int mi = 0; mi < 4; mi++) {
                const int r0 = wm * 64 + mi * 16 + lr;
                af[mi][0] = f2tf(cA[r0 * PROWF + kk]);
                af[mi][1] = f2tf(cA[(r0 + 8) * PROWF + kk]);
                af[mi][2] = f2tf(cA[r0 * PROWF + kk + 4]);
                af[mi][3] = f2tf(cA[(r0 + 8) * PROWF + kk + 4]);
            }
            #pragma unroll
            for (int ni = 0; ni < 4; ni++) {
                const int n0 = wn * 32 + ni * 8 + lr;
                const unsigned b0 = f2tf(cB[n0 * PROWF + kk]);
                const unsigned b1 = f2tf(cB[n0 * PROWF + kk + 4]);
                #pragma unroll
                for (int mi = 0; mi < 4; mi++)
                    mma_tf(acc[mi][ni], af[mi][0], af[mi][1],
                           af[mi][2], af[mi][3], b0, b1);
            }
        }
        __syncthreads();
    }

    const int rA = bm + wm * 64 + lr;
    #pragma unroll
    for (int mi = 0; mi < 4; mi++) {
        const int r0 = rA + mi * 16, r1 = r0 + 8;
        #pragma unroll
        for (int ni = 0; ni < 4; ni++) {
            const int col = bn + wn * 32 + ni * 8 + lc * 2;
            const float b0 = bias[col], b1 = bias[col + 1];
            *(float2*)(out + (size_t)r0 * EE + col) =
                make_float2(acc[mi][ni][0] + b0, acc[mi][ni][1] + b1);
            *(float2*)(out + (size_t)r1 * EE + col) =
                make_float2(acc[mi][ni][2] + b0, acc[mi][ni][3] + b1);
        }
    }
}

#define ATTN_SMEM (8 * PLANE * 2)         // 73728 bytes
#define PROJ_SMEM (4 * FPLANE * 4)        // 73728 bytes

// ---------------------------------------------------------------------------
extern "C" void kernel_launch(void* const* d_in, const int* in_sizes, int n_in,
                              void* d_out, int out_size)
{
    const float* q  = (const float*)d_in[0];
    const float* k  = (const float*)d_in[1];
    const float* v  = (const float*)d_in[2];
    const float* qs = (const float*)d_in[3];
    const float* ks = (const float*)d_in[4];
    const float* pw = (const float*)d_in[5];
    const float* pb = (const float*)d_in[6];
    float* out = (float*)d_out;

    cudaFuncSetAttribute(attn_kernel,
        cudaFuncAttributeMaxDynamicSharedMemorySize, ATTN_SMEM);
    cudaFuncSetAttribute(proj_kernel,
        cudaFuncAttributeMaxDynamicSharedMemorySize, PROJ_SMEM);

    prep_kernel<<<BB * NN, 384>>>(q, k, v, qs, ks);
    attn_kernel<<<dim3(NN / BR, BB * HH), 256, ATTN_SMEM>>>();
    proj_kernel<<<dim3(EE / 128, (BB * NN) / 128), 256, PROJ_SMEM>>>(pw, pb, out);
}